// round 9
// baseline (speedup 1.0000x reference)
#include <cuda_runtime.h>
#include <cuda_bf16.h>
#include <math.h>

// Problem constants
#define BB 2
#define NN 8192
#define EE 768
#define HH 12
#define DD 64
#define MTOT (BB*NN)        // 16384

// Scratch (device globals: allocation-guard safe)
__device__ float g_Q[BB*NN*EE];
__device__ float g_K[BB*NN*EE];
__device__ float g_V[BB*NN*EE];
__device__ float g_O4[BB*NN*EE];
__device__ float g_part[32*BB*EE];
__device__ float g_inv[BB*EE];

// bf16 split planes (3-way exact decomposition), reused GEMM-to-GEMM
#define ASZ (MTOT*EE)
#define WSZ (EE*EE)
__device__ unsigned short g_sA[3*ASZ];   // ~75 MB
__device__ unsigned short g_sW[3*WSZ];   // ~3.5 MB

// ---------------------------------------------------------------------------
__global__ void zero_O4_kernel() {
    size_t i = (size_t)blockIdx.x * blockDim.x + threadIdx.x;
    ((float4*)g_O4)[i] = make_float4(0.f, 0.f, 0.f, 0.f);
}

// ---------------------------------------------------------------------------
// bf16 3-way exact split helpers
// ---------------------------------------------------------------------------
__device__ __forceinline__ unsigned short bfr(float x) {
    __nv_bfloat16 h = __float2bfloat16_rn(x);
    return *(unsigned short*)&h;
}
__device__ __forceinline__ float bff(unsigned short u) {
    __nv_bfloat16 h = *(__nv_bfloat16*)&u;
    return __bfloat162float(h);
}
__device__ __forceinline__ void split3(float x, unsigned short &a, unsigned short &b, unsigned short &c) {
    a = bfr(x);          float r1 = x - bff(a);
    b = bfr(r1);         float r2 = r1 - bff(b);
    c = bfr(r2);
}

// Split A[16384,768] (optionally scaled per (b,k) by colscale) into 3 planes.
__global__ void splitA_kernel(const float* __restrict__ A,
                              const float* __restrict__ colscale) {
    int i = blockIdx.x*256 + threadIdx.x;          // float4 index, 3145728 total
    float4 av = ((const float4*)A)[i];
    if (colscale) {
        int kq = i % 192;
        int m  = i / 192;
        float4 cs = ((const float4*)colscale)[(m >> 13)*192 + kq];
        av.x *= cs.x; av.y *= cs.y; av.z *= cs.z; av.w *= cs.w;
    }
    ushort4 sa, sb, sc;
    split3(av.x, sa.x, sb.x, sc.x); split3(av.y, sa.y, sb.y, sc.y);
    split3(av.z, sa.z, sb.z, sc.z); split3(av.w, sa.w, sb.w, sc.w);
    ((ushort4*)g_sA)[i]           = sa;
    ((ushort4*)(g_sA + ASZ))[i]   = sb;
    ((ushort4*)(g_sA + 2*ASZ))[i] = sc;
}

// Split W[768,768] into 3 planes.
__global__ void splitW_kernel(const float* __restrict__ W) {
    int i = blockIdx.x*256 + threadIdx.x;          // float4 index, 147456 total
    float4 wv = ((const float4*)W)[i];
    ushort4 sa, sb, sc;
    split3(wv.x, sa.x, sb.x, sc.x); split3(wv.y, sa.y, sb.y, sc.y);
    split3(wv.z, sa.z, sb.z, sc.z); split3(wv.w, sa.w, sb.w, sc.w);
    ((ushort4*)g_sW)[i]           = sa;
    ((ushort4*)(g_sW + WSZ))[i]   = sb;
    ((ushort4*)(g_sW + 2*WSZ))[i] = sc;
}

// ---------------------------------------------------------------------------
// bf16x6 tensor-core GEMM, precomputed splits, double-buffered.
// C[m,n] = alpha * ( [split-sum products] + bias[n] )
// CTA 128x128, K-block 32, 8 warps (4Mx2N), warp tile 32x64, m16n8k16 MMA.
// Per-K-block chain restart + RN respill (validated in R8: rel_err 3.6e-5).
// ---------------------------------------------------------------------------
#define BLDA 40                    // smem row stride in bf16 (80B)
#define SPL  (128*BLDA)            // ushorts per plane buffer
#define SPLB (SPL*2u)              // bytes per plane buffer (10240)
#define STG  (6*SPL)               // ushorts per stage (6 planes)
#define STGB (6*SPLB)              // bytes per stage
#define GEMM_SMEM_BYTES (2*STGB)   // 122880

__device__ __forceinline__ void mma_bf16(float* acc, const unsigned* a, unsigned b0, unsigned b1) {
    asm volatile(
        "mma.sync.aligned.m16n8k16.row.col.f32.bf16.bf16.f32 "
        "{%0,%1,%2,%3}, {%4,%5,%6,%7}, {%8,%9}, {%0,%1,%2,%3};"
        : "+f"(acc[0]), "+f"(acc[1]), "+f"(acc[2]), "+f"(acc[3])
        : "r"(a[0]), "r"(a[1]), "r"(a[2]), "r"(a[3]), "r"(b0), "r"(b1));
}
__device__ __forceinline__ void mma_bf16_z(float* d, const unsigned* a, unsigned b0, unsigned b1) {
    asm volatile(
        "mma.sync.aligned.m16n8k16.row.col.f32.bf16.bf16.f32 "
        "{%0,%1,%2,%3}, {%4,%5,%6,%7}, {%8,%9}, {%10,%11,%12,%13};"
        : "=f"(d[0]), "=f"(d[1]), "=f"(d[2]), "=f"(d[3])
        : "r"(a[0]), "r"(a[1]), "r"(a[2]), "r"(a[3]), "r"(b0), "r"(b1),
          "f"(0.f), "f"(0.f), "f"(0.f), "f"(0.f));
}
__device__ __forceinline__ void ldsm4(unsigned* d, unsigned addr) {
    asm volatile("ldmatrix.sync.aligned.m8n8.x4.shared.b16 {%0,%1,%2,%3}, [%4];"
                 : "=r"(d[0]), "=r"(d[1]), "=r"(d[2]), "=r"(d[3]) : "r"(addr));
}

__global__ __launch_bounds__(256) void gemm768_tc2_kernel(
    const float* __restrict__ bias, float alpha, float* __restrict__ C)
{
    extern __shared__ unsigned short smu[];

    const int tid  = threadIdx.x;
    const int lane = tid & 31;
    const int wid  = tid >> 5;
    const int warp_m = wid & 3;    // 4 warps along M (32 each)
    const int warp_n = wid >> 2;   // 2 warps along N (64 each)
    const int m0 = blockIdx.y * 128;
    const int n0 = blockIdx.x * 128;

    const int lcol = tid & 3;      // uint4 (8 bf16) index along k (32 wide)
    const int lrow = tid >> 2;     // 0..63, second pass +64

    float acc[2][8][4];            // master accumulator (RN adds)
    float accm[2][8][4];           // per-K-block chain accumulator
#pragma unroll
    for (int mt = 0; mt < 2; ++mt)
#pragma unroll
        for (int nt = 0; nt < 8; ++nt)
#pragma unroll
            for (int r = 0; r < 4; ++r) acc[mt][nt][r] = 0.f;

    const unsigned smbase = (unsigned)__cvta_generic_to_shared(smu);
    const unsigned a_off = (unsigned)((warp_m*32 + (lane & 15))*80) + ((lane >> 4) << 4);
    const unsigned b_off = (unsigned)((warp_n*64 + (lane & 15))*80) + ((lane >> 4) << 4);

    // stage loader: global (precomputed planes) -> smem stage buf
#define LOAD_STAGE(t, buf)                                                         \
    {                                                                              \
        const int kb_ = (t)*32;                                                    \
        unsigned short* dst_ = smu + (buf)*STG;                                    \
        _Pragma("unroll")                                                          \
        for (int pl = 0; pl < 3; ++pl) {                                           \
            const unsigned short* srcA_ = g_sA + (size_t)pl*ASZ + (size_t)m0*768 + kb_; \
            const unsigned short* srcW_ = g_sW + (size_t)pl*WSZ + (size_t)n0*768 + kb_; \
            _Pragma("unroll")                                                      \
            for (int l = 0; l < 2; ++l) {                                          \
                int r_ = lrow + l*64;                                              \
                *(uint4*)(dst_ + pl*SPL + r_*BLDA + lcol*8) =                      \
                    *(const uint4*)(srcA_ + (size_t)r_*768 + lcol*8);              \
                *(uint4*)(dst_ + (3+pl)*SPL + r_*BLDA + lcol*8) =                  \
                    *(const uint4*)(srcW_ + (size_t)r_*768 + lcol*8);              \
            }                                                                      \
        }                                                                          \
    }

    LOAD_STAGE(0, 0);
    __syncthreads();

    for (int t = 0; t < 24; ++t) {
        const int buf = t & 1;
        if (t < 23) LOAD_STAGE(t + 1, buf ^ 1);

        const unsigned stg = smbase + (unsigned)buf*STGB;
#pragma unroll
        for (int ks = 0; ks < 2; ++ks) {
            unsigned af[2][3][4];
#pragma unroll
            for (int mt = 0; mt < 2; ++mt)
#pragma unroll
                for (int s = 0; s < 3; ++s)
                    ldsm4(af[mt][s], stg + s*SPLB + a_off + mt*(16*80) + ks*32);

#pragma unroll
            for (int p = 0; p < 4; ++p) {
                unsigned bf[3][4];
#pragma unroll
                for (int s = 0; s < 3; ++s)
                    ldsm4(bf[s], stg + (3+s)*SPLB + b_off + p*(16*80) + ks*32);
#pragma unroll
                for (int mt = 0; mt < 2; ++mt)
#pragma unroll
                    for (int h = 0; h < 2; ++h) {
                        float* ac = accm[mt][p*2 + h];
                        if (ks == 0)
                            mma_bf16_z(ac, af[mt][1], bf[1][h], bf[1][h+2]); // b*b (restart)
                        else
                            mma_bf16(ac, af[mt][1], bf[1][h], bf[1][h+2]);   // b*b
                        mma_bf16(ac, af[mt][2], bf[0][h], bf[0][h+2]);  // c*a
                        mma_bf16(ac, af[mt][0], bf[2][h], bf[2][h+2]);  // a*c
                        mma_bf16(ac, af[mt][1], bf[0][h], bf[0][h+2]);  // b*a
                        mma_bf16(ac, af[mt][0], bf[1][h], bf[1][h+2]);  // a*b
                        mma_bf16(ac, af[mt][0], bf[0][h], bf[0][h+2]);  // a*a
                    }
            }
        }
        // RN respill
#pragma unroll
        for (int mt = 0; mt < 2; ++mt)
#pragma unroll
            for (int nt = 0; nt < 8; ++nt)
#pragma unroll
                for (int r = 0; r < 4; ++r)
                    acc[mt][nt][r] += accm[mt][nt][r];
        __syncthreads();
    }
#undef LOAD_STAGE

    // Epilogue: (acc + bias) * alpha, coalesced float2 stores
    const int r0 = lane >> 2;
    const int c0 = (lane & 3) * 2;
#pragma unroll
    for (int mt = 0; mt < 2; ++mt) {
#pragma unroll
        for (int nt = 0; nt < 8; ++nt) {
            int col = n0 + warp_n*64 + nt*8 + c0;
            float b0 = bias[col], b1 = bias[col + 1];
            int row_t = m0 + warp_m*32 + mt*16 + r0;
            float2 v0, v1;
            v0.x = (acc[mt][nt][0] + b0)*alpha; v0.y = (acc[mt][nt][1] + b1)*alpha;
            v1.x = (acc[mt][nt][2] + b0)*alpha; v1.y = (acc[mt][nt][3] + b1)*alpha;
            *(float2*)(C + (size_t)row_t*768 + col)       = v0;
            *(float2*)(C + (size_t)(row_t + 8)*768 + col) = v1;
        }
    }
}

// ---------------------------------------------------------------------------
// Dilated flash attention (scalar fp32 — best verified version).
// ---------------------------------------------------------------------------
#define ATTN_SMEM_FLOATS (64*132 + 64*68 + 64*64 + 64*132)
#define ATTN_SMEM_BYTES  (ATTN_SMEM_FLOATS*4)

__global__ __launch_bounds__(256, 2) void attn_kernel()
{
    extern __shared__ float sm[];
    float* Qst = sm;                      // [d=64][m=128] ld 132
    float* Kst = sm + 64*132;             // [d=64][n=64]  ld 68
    float* Vs  = Kst + 64*68;             // [k=64][d=64]  ld 64
    float* Pst = Vs + 64*64;              // [k=64][m=128] ld 132

    const int tid = threadIdx.x;
    const int tx = tid & 15, ty = tid >> 4;

    const int inst = blockIdx.y;
    int grp, b, seg, hl;
    if (inst < 32)      { grp = 0; b = inst >> 4;        seg = (inst >> 2) & 3; hl = inst & 3; }
    else if (inst < 48) { int r = inst - 32; grp = 1; b = r >> 3; seg = (r >> 2) & 1; hl = r & 3; }
    else                { int r = inst - 48; grp = 2; b = r >> 2; seg = 0;            hl = r & 3; }
    const int rate = 1 << grp;
    const int slen = 2048 << grp;
    const int off  = grp;
    const int head = grp*4 + hl;
    const int q0   = blockIdx.x * 128;

    const size_t base = (size_t)b*NN*EE + (size_t)(seg*slen + off)*EE + head*DD;
    const int stride = rate * EE;

#pragma unroll
    for (int l = 0; l < 8; ++l) {
        int idx = tid + l*256;
        int row = idx >> 4;
        int c4  = idx & 15;
        float4 v = *(const float4*)(g_Q + base + (size_t)(q0 + row)*stride + c4*4);
        Qst[(c4*4+0)*132 + row] = v.x;
        Qst[(c4*4+1)*132 + row] = v.y;
        Qst[(c4*4+2)*132 + row] = v.z;
        Qst[(c4*4+3)*132 + row] = v.w;
    }

    float m_i[8], l_i[8], O[8][4];
#pragma unroll
    for (int i = 0; i < 8; ++i) {
        m_i[i] = -1e30f; l_i[i] = 0.f;
#pragma unroll
        for (int j = 0; j < 4; ++j) O[i][j] = 0.f;
    }

    for (int kt = 0; kt < 32; ++kt) {
        const int k0 = kt * 64;
        __syncthreads();
#pragma unroll
        for (int l = 0; l < 4; ++l) {
            int idx = tid + l*256;
            int row = idx >> 4;
            int c4  = idx & 15;
            float4 kv = *(const float4*)(g_K + base + (size_t)(k0 + row)*stride + c4*4);
            Kst[(c4*4+0)*68 + row] = kv.x;
            Kst[(c4*4+1)*68 + row] = kv.y;
            Kst[(c4*4+2)*68 + row] = kv.z;
            Kst[(c4*4+3)*68 + row] = kv.w;
            float4 vv = *(const float4*)(g_V + base + (size_t)(k0 + row)*stride + c4*4);
            *(float4*)(Vs + row*64 + c4*4) = vv;
        }
        __syncthreads();

        float S[8][4];
#pragma unroll
        for (int i = 0; i < 8; ++i)
#pragma unroll
            for (int j = 0; j < 4; ++j) S[i][j] = 0.f;
#pragma unroll 8
        for (int k = 0; k < 64; ++k) {
            float4 a0 = *(const float4*)(Qst + k*132 + ty*8);
            float4 a1 = *(const float4*)(Qst + k*132 + ty*8 + 4);
            float4 bv = *(const float4*)(Kst + k*68 + tx*4);
            float a[8] = {a0.x,a0.y,a0.z,a0.w,a1.x,a1.y,a1.z,a1.w};
#pragma unroll
            for (int i = 0; i < 8; ++i) {
                S[i][0] += a[i]*bv.x;
                S[i][1] += a[i]*bv.y;
                S[i][2] += a[i]*bv.z;
                S[i][3] += a[i]*bv.w;
            }
        }

#pragma unroll
        for (int i = 0; i < 8; ++i) {
            float mx = fmaxf(fmaxf(S[i][0], S[i][1]), fmaxf(S[i][2], S[i][3]));
#pragma unroll
            for (int w = 8; w > 0; w >>= 1)
                mx = fmaxf(mx, __shfl_xor_sync(0xffffffffu, mx, w));
            float mnew = fmaxf(m_i[i], mx);
            float corr = __expf(m_i[i] - mnew);
            m_i[i] = mnew;
            float rs = 0.f;
#pragma unroll
            for (int j = 0; j < 4; ++j) {
                float p = __expf(S[i][j] - mnew);
                S[i][j] = p;
                rs += p;
            }
#pragma unroll
            for (int w = 8; w > 0; w >>= 1)
                rs += __shfl_xor_sync(0xffffffffu, rs, w);
            l_i[i] = l_i[i]*corr + rs;
#pragma unroll
            for (int j = 0; j < 4; ++j) {
                O[i][j] *= corr;
                Pst[(tx*4+j)*132 + ty*8 + i] = S[i][j];
            }
        }
        __syncthreads();

#pragma unroll 8
        for (int k = 0; k < 64; ++k) {
            float4 p0 = *(const float4*)(Pst + k*132 + ty*8);
            float4 p1 = *(const float4*)(Pst + k*132 + ty*8 + 4);
            float4 vv = *(const float4*)(Vs + k*64 + tx*4);
            float p[8] = {p0.x,p0.y,p0.z,p0.w,p1.x,p1.y,p1.z,p1.w};
#pragma unroll
            for (int i = 0; i < 8; ++i) {
                O[i][0] += p[i]*vv.x;
                O[i][1] += p[i]*vv.y;
                O[i][2] += p[i]*vv.z;
                O[i][3] += p[i]*vv.w;
            }
        }
    }

#pragma unroll
    for (int i = 0; i < 8; ++i) {
        float inv = 1.0f / l_i[i];
        float4 o;
        o.x = O[i][0]*inv; o.y = O[i][1]*inv; o.z = O[i][2]*inv; o.w = O[i][3]*inv;
        int p = q0 + ty*8 + i;
        *(float4*)(g_O4 + base + (size_t)p*stride + tx*4) = o;
    }
}

// ---------------------------------------------------------------------------
// denom[b,c] = sum_n O4[b,n,c]; two-phase deterministic reduction
// ---------------------------------------------------------------------------
__global__ void colsum_part_kernel()
{
    int chunk = blockIdx.x;
    int bc    = blockIdx.y;
    int b  = bc / 3;
    int c  = (bc % 3)*256 + threadIdx.x;
    const float* p = g_O4 + ((size_t)b*NN + chunk*256)*EE + c;
    float s = 0.f;
#pragma unroll 8
    for (int n = 0; n < 256; ++n) {
        s += *p;
        p += EE;
    }
    g_part[chunk*(BB*EE) + b*EE + c] = s;
}

__global__ void colsum_reduce_kernel()
{
    int i = blockIdx.x*256 + threadIdx.x;
    float s = 0.f;
#pragma unroll
    for (int ch = 0; ch < 32; ++ch) s += g_part[ch*(BB*EE) + i];
    g_inv[i] = 1.0f / s;
}

// ---------------------------------------------------------------------------
extern "C" void kernel_launch(void* const* d_in, const int* in_sizes, int n_in,
                              void* d_out, int out_size)
{
    const float* query = (const float*)d_in[0];
    const float* key   = (const float*)d_in[1];
    const float* value = (const float*)d_in[2];
    const float* Wq = (const float*)d_in[3];
    const float* bq = (const float*)d_in[4];
    const float* Wk = (const float*)d_in[5];
    const float* bk = (const float*)d_in[6];
    const float* Wv = (const float*)d_in[7];
    const float* bv = (const float*)d_in[8];
    const float* Wo = (const float*)d_in[9];
    const float* bo = (const float*)d_in[10];
    float* out = (float*)d_out;

    float *pQ, *pK, *pV, *pO4, *pInv;
    cudaGetSymbolAddress((void**)&pQ,   g_Q);
    cudaGetSymbolAddress((void**)&pK,   g_K);
    cudaGetSymbolAddress((void**)&pV,   g_V);
    cudaGetSymbolAddress((void**)&pO4,  g_O4);
    cudaGetSymbolAddress((void**)&pInv, g_inv);

    cudaFuncSetAttribute(attn_kernel,
                         cudaFuncAttributeMaxDynamicSharedMemorySize,
                         ATTN_SMEM_BYTES);
    cudaFuncSetAttribute(gemm768_tc2_kernel,
                         cudaFuncAttributeMaxDynamicSharedMemorySize,
                         GEMM_SMEM_BYTES);

    dim3 gg(6, 128);

    // 1. zero scatter buffer
    zero_O4_kernel<<<12288, 256>>>();

    // 2. projections: split once, GEMM clean (Q pre-scaled by 1/8 after bias)
    splitW_kernel<<<576, 256>>>(Wq);
    splitA_kernel<<<12288, 256>>>(query, nullptr);
    gemm768_tc2_kernel<<<gg, 256, GEMM_SMEM_BYTES>>>(bq, 0.125f, pQ);

    splitW_kernel<<<576, 256>>>(Wk);
    splitA_kernel<<<12288, 256>>>(key, nullptr);
    gemm768_tc2_kernel<<<gg, 256, GEMM_SMEM_BYTES>>>(bk, 1.0f, pK);

    splitW_kernel<<<576, 256>>>(Wv);
    splitA_kernel<<<12288, 256>>>(value, nullptr);
    gemm768_tc2_kernel<<<gg, 256, GEMM_SMEM_BYTES>>>(bv, 1.0f, pV);

    // 3. dilated attention (56 instances x 16 q-tiles)
    attn_kernel<<<dim3(16, 56), 256, ATTN_SMEM_BYTES>>>();

    // 4. sequence-sum normalization factors
    colsum_part_kernel<<<dim3(32, 6), 256>>>();
    colsum_reduce_kernel<<<6, 256>>>();

    // 5. output projection; 1/denom folded into the A-split
    splitW_kernel<<<576, 256>>>(Wo);
    splitA_kernel<<<12288, 256>>>(pO4, pInv);
    gemm768_tc2_kernel<<<gg, 256, GEMM_SMEM_BYTES>>>(bo, 1.0f, out);
}

// round 10
// speedup vs baseline: 1.0447x; 1.0447x over previous
#include <cuda_runtime.h>
#include <cuda_bf16.h>
#include <math.h>

// Problem constants
#define BB 2
#define NN 8192
#define EE 768
#define HH 12
#define DD 64
#define MTOT (BB*NN)        // 16384

// Scratch (device globals: allocation-guard safe)
__device__ float g_Q[BB*NN*EE];
__device__ float g_K[BB*NN*EE];
__device__ float g_V[BB*NN*EE];
__device__ float g_O4[BB*NN*EE];
__device__ float g_part[32*BB*EE];
__device__ float g_inv[BB*EE];

// bf16 split planes (3-way exact decomposition), reused GEMM-to-GEMM
#define ASZ (MTOT*EE)
#define WSZ (EE*EE)
__device__ unsigned short g_sA[3*ASZ];   // ~75 MB
__device__ unsigned short g_sW[3*WSZ];   // ~3.5 MB

// ---------------------------------------------------------------------------
__global__ void zero_O4_kernel() {
    size_t i = (size_t)blockIdx.x * blockDim.x + threadIdx.x;
    ((float4*)g_O4)[i] = make_float4(0.f, 0.f, 0.f, 0.f);
}

// ---------------------------------------------------------------------------
// bf16 3-way exact split helpers
// ---------------------------------------------------------------------------
__device__ __forceinline__ unsigned short bfr(float x) {
    __nv_bfloat16 h = __float2bfloat16_rn(x);
    return *(unsigned short*)&h;
}
__device__ __forceinline__ float bff(unsigned short u) {
    __nv_bfloat16 h = *(__nv_bfloat16*)&u;
    return __bfloat162float(h);
}
__device__ __forceinline__ void split3(float x, unsigned short &a, unsigned short &b, unsigned short &c) {
    a = bfr(x);          float r1 = x - bff(a);
    b = bfr(r1);         float r2 = r1 - bff(b);
    c = bfr(r2);
}

// Split A[16384,768] (optionally scaled per (b,k) by colscale) into 3 planes.
__global__ void splitA_kernel(const float* __restrict__ A,
                              const float* __restrict__ colscale) {
    int i = blockIdx.x*256 + threadIdx.x;          // float4 index, 3145728 total
    float4 av = ((const float4*)A)[i];
    if (colscale) {
        int kq = i % 192;
        int m  = i / 192;
        float4 cs = ((const float4*)colscale)[(m >> 13)*192 + kq];
        av.x *= cs.x; av.y *= cs.y; av.z *= cs.z; av.w *= cs.w;
    }
    ushort4 sa, sb, sc;
    split3(av.x, sa.x, sb.x, sc.x); split3(av.y, sa.y, sb.y, sc.y);
    split3(av.z, sa.z, sb.z, sc.z); split3(av.w, sa.w, sb.w, sc.w);
    ((ushort4*)g_sA)[i]           = sa;
    ((ushort4*)(g_sA + ASZ))[i]   = sb;
    ((ushort4*)(g_sA + 2*ASZ))[i] = sc;
}

// Split W[768,768] into 3 planes.
__global__ void splitW_kernel(const float* __restrict__ W) {
    int i = blockIdx.x*256 + threadIdx.x;          // float4 index, 147456 total
    float4 wv = ((const float4*)W)[i];
    ushort4 sa, sb, sc;
    split3(wv.x, sa.x, sb.x, sc.x); split3(wv.y, sa.y, sb.y, sc.y);
    split3(wv.z, sa.z, sb.z, sc.z); split3(wv.w, sa.w, sb.w, sc.w);
    ((ushort4*)g_sW)[i]           = sa;
    ((ushort4*)(g_sW + WSZ))[i]   = sb;
    ((ushort4*)(g_sW + 2*WSZ))[i] = sc;
}

// ---------------------------------------------------------------------------
// bf16x6 tensor-core GEMM, precomputed splits, double-buffered, 512 threads.
// CTA 128x128, K-block 32, 16 warps (4Mx4N), warp tile 32x32, m16n8k16 MMA.
// Per-K-block chain restart + RN respill (validated: rel_err 3.6e-5).
// ---------------------------------------------------------------------------
#define BLDA 40                    // smem row stride in bf16 (80B)
#define SPL  (128*BLDA)            // ushorts per plane buffer
#define SPLB (SPL*2u)              // bytes per plane buffer (10240)
#define STG  (6*SPL)               // ushorts per stage (6 planes)
#define STGB (6*SPLB)              // bytes per stage
#define GEMM_SMEM_BYTES (2*STGB)   // 122880

__device__ __forceinline__ void mma_bf16(float* acc, const unsigned* a, unsigned b0, unsigned b1) {
    asm volatile(
        "mma.sync.aligned.m16n8k16.row.col.f32.bf16.bf16.f32 "
        "{%0,%1,%2,%3}, {%4,%5,%6,%7}, {%8,%9}, {%0,%1,%2,%3};"
        : "+f"(acc[0]), "+f"(acc[1]), "+f"(acc[2]), "+f"(acc[3])
        : "r"(a[0]), "r"(a[1]), "r"(a[2]), "r"(a[3]), "r"(b0), "r"(b1));
}
__device__ __forceinline__ void mma_bf16_z(float* d, const unsigned* a, unsigned b0, unsigned b1) {
    asm volatile(
        "mma.sync.aligned.m16n8k16.row.col.f32.bf16.bf16.f32 "
        "{%0,%1,%2,%3}, {%4,%5,%6,%7}, {%8,%9}, {%10,%11,%12,%13};"
        : "=f"(d[0]), "=f"(d[1]), "=f"(d[2]), "=f"(d[3])
        : "r"(a[0]), "r"(a[1]), "r"(a[2]), "r"(a[3]), "r"(b0), "r"(b1),
          "f"(0.f), "f"(0.f), "f"(0.f), "f"(0.f));
}
__device__ __forceinline__ void ldsm4(unsigned* d, unsigned addr) {
    asm volatile("ldmatrix.sync.aligned.m8n8.x4.shared.b16 {%0,%1,%2,%3}, [%4];"
                 : "=r"(d[0]), "=r"(d[1]), "=r"(d[2]), "=r"(d[3]) : "r"(addr));
}

__global__ __launch_bounds__(512) void gemm768_tc2_kernel(
    const float* __restrict__ bias, float alpha, float* __restrict__ C)
{
    extern __shared__ unsigned short smu[];

    const int tid  = threadIdx.x;
    const int lane = tid & 31;
    const int wid  = tid >> 5;     // 0..15
    const int warp_m = wid & 3;    // 4 warps along M (32 each)
    const int warp_n = wid >> 2;   // 4 warps along N (32 each)
    const int m0 = blockIdx.y * 128;
    const int n0 = blockIdx.x * 128;

    // loader mapping: 512 threads cover one full plane row-set per pass
    const int lrow = tid >> 2;     // 0..127
    const int lcol = tid & 3;      // uint4 (8 bf16) index along 32-wide k

    float acc[2][4][4];            // master accumulator (RN adds)
    float accm[2][4][4];           // per-K-block chain accumulator
#pragma unroll
    for (int mt = 0; mt < 2; ++mt)
#pragma unroll
        for (int nt = 0; nt < 4; ++nt)
#pragma unroll
            for (int r = 0; r < 4; ++r) acc[mt][nt][r] = 0.f;

    const unsigned smbase = (unsigned)__cvta_generic_to_shared(smu);
    const unsigned a_off = (unsigned)((warp_m*32 + (lane & 15))*80) + ((lane >> 4) << 4);
    const unsigned b_off = (unsigned)((warp_n*32 + (lane & 15))*80) + ((lane >> 4) << 4);

#define LOAD_STAGE(t, buf)                                                          \
    {                                                                               \
        const int kb_ = (t)*32;                                                     \
        unsigned short* dst_ = smu + (buf)*STG;                                     \
        _Pragma("unroll")                                                           \
        for (int pl = 0; pl < 3; ++pl) {                                            \
            *(uint4*)(dst_ + pl*SPL + lrow*BLDA + lcol*8) =                         \
                *(const uint4*)(g_sA + (size_t)pl*ASZ + (size_t)(m0 + lrow)*768 + kb_ + lcol*8); \
            *(uint4*)(dst_ + (3+pl)*SPL + lrow*BLDA + lcol*8) =                     \
                *(const uint4*)(g_sW + (size_t)pl*WSZ + (size_t)(n0 + lrow)*768 + kb_ + lcol*8); \
        }                                                                           \
    }

    LOAD_STAGE(0, 0);
    __syncthreads();

    for (int t = 0; t < 24; ++t) {
        const int buf = t & 1;
        if (t < 23) LOAD_STAGE(t + 1, buf ^ 1);

        const unsigned stg = smbase + (unsigned)buf*STGB;
#pragma unroll
        for (int ks = 0; ks < 2; ++ks) {
            unsigned af[2][3][4];
#pragma unroll
            for (int mt = 0; mt < 2; ++mt)
#pragma unroll
                for (int s = 0; s < 3; ++s)
                    ldsm4(af[mt][s], stg + s*SPLB + a_off + mt*(16*80) + ks*32);

#pragma unroll
            for (int p = 0; p < 2; ++p) {       // two 16-row B groups (32 cols)
                unsigned bf[3][4];
#pragma unroll
                for (int s = 0; s < 3; ++s)
                    ldsm4(bf[s], stg + (3+s)*SPLB + b_off + p*(16*80) + ks*32);
#pragma unroll
                for (int mt = 0; mt < 2; ++mt)
#pragma unroll
                    for (int h = 0; h < 2; ++h) {
                        float* ac = accm[mt][p*2 + h];
                        if (ks == 0)
                            mma_bf16_z(ac, af[mt][1], bf[1][h], bf[1][h+2]); // b*b (restart)
                        else
                            mma_bf16(ac, af[mt][1], bf[1][h], bf[1][h+2]);   // b*b
                        mma_bf16(ac, af[mt][2], bf[0][h], bf[0][h+2]);  // c*a
                        mma_bf16(ac, af[mt][0], bf[2][h], bf[2][h+2]);  // a*c
                        mma_bf16(ac, af[mt][1], bf[0][h], bf[0][h+2]);  // b*a
                        mma_bf16(ac, af[mt][0], bf[1][h], bf[1][h+2]);  // a*b
                        mma_bf16(ac, af[mt][0], bf[0][h], bf[0][h+2]);  // a*a
                    }
            }
        }
        // RN respill
#pragma unroll
        for (int mt = 0; mt < 2; ++mt)
#pragma unroll
            for (int nt = 0; nt < 4; ++nt)
#pragma unroll
                for (int r = 0; r < 4; ++r)
                    acc[mt][nt][r] += accm[mt][nt][r];
        __syncthreads();
    }
#undef LOAD_STAGE

    // Epilogue: (acc + bias) * alpha, coalesced float2 stores
    const int r0 = lane >> 2;
    const int c0 = (lane & 3) * 2;
#pragma unroll
    for (int mt = 0; mt < 2; ++mt) {
#pragma unroll
        for (int nt = 0; nt < 4; ++nt) {
            int col = n0 + warp_n*32 + nt*8 + c0;
            float b0 = bias[col], b1 = bias[col + 1];
            int row_t = m0 + warp_m*32 + mt*16 + r0;
            float2 v0, v1;
            v0.x = (acc[mt][nt][0] + b0)*alpha; v0.y = (acc[mt][nt][1] + b1)*alpha;
            v1.x = (acc[mt][nt][2] + b0)*alpha; v1.y = (acc[mt][nt][3] + b1)*alpha;
            *(float2*)(C + (size_t)row_t*768 + col)       = v0;
            *(float2*)(C + (size_t)(row_t + 8)*768 + col) = v1;
        }
    }
}

// ---------------------------------------------------------------------------
// Dilated flash attention (scalar fp32 — best verified version).
// ---------------------------------------------------------------------------
#define ATTN_SMEM_FLOATS (64*132 + 64*68 + 64*64 + 64*132)
#define ATTN_SMEM_BYTES  (ATTN_SMEM_FLOATS*4)

__global__ __launch_bounds__(256, 2) void attn_kernel()
{
    extern __shared__ float sm[];
    float* Qst = sm;                      // [d=64][m=128] ld 132
    float* Kst = sm + 64*132;             // [d=64][n=64]  ld 68
    float* Vs  = Kst + 64*68;             // [k=64][d=64]  ld 64
    float* Pst = Vs + 64*64;              // [k=64][m=128] ld 132

    const int tid = threadIdx.x;
    const int tx = tid & 15, ty = tid >> 4;

    const int inst = blockIdx.y;
    int grp, b, seg, hl;
    if (inst < 32)      { grp = 0; b = inst >> 4;        seg = (inst >> 2) & 3; hl = inst & 3; }
    else if (inst < 48) { int r = inst - 32; grp = 1; b = r >> 3; seg = (r >> 2) & 1; hl = r & 3; }
    else                { int r = inst - 48; grp = 2; b = r >> 2; seg = 0;            hl = r & 3; }
    const int rate = 1 << grp;
    const int slen = 2048 << grp;
    const int off  = grp;
    const int head = grp*4 + hl;
    const int q0   = blockIdx.x * 128;

    const size_t base = (size_t)b*NN*EE + (size_t)(seg*slen + off)*EE + head*DD;
    const int stride = rate * EE;

#pragma unroll
    for (int l = 0; l < 8; ++l) {
        int idx = tid + l*256;
        int row = idx >> 4;
        int c4  = idx & 15;
        float4 v = *(const float4*)(g_Q + base + (size_t)(q0 + row)*stride + c4*4);
        Qst[(c4*4+0)*132 + row] = v.x;
        Qst[(c4*4+1)*132 + row] = v.y;
        Qst[(c4*4+2)*132 + row] = v.z;
        Qst[(c4*4+3)*132 + row] = v.w;
    }

    float m_i[8], l_i[8], O[8][4];
#pragma unroll
    for (int i = 0; i < 8; ++i) {
        m_i[i] = -1e30f; l_i[i] = 0.f;
#pragma unroll
        for (int j = 0; j < 4; ++j) O[i][j] = 0.f;
    }

    for (int kt = 0; kt < 32; ++kt) {
        const int k0 = kt * 64;
        __syncthreads();
#pragma unroll
        for (int l = 0; l < 4; ++l) {
            int idx = tid + l*256;
            int row = idx >> 4;
            int c4  = idx & 15;
            float4 kv = *(const float4*)(g_K + base + (size_t)(k0 + row)*stride + c4*4);
            Kst[(c4*4+0)*68 + row] = kv.x;
            Kst[(c4*4+1)*68 + row] = kv.y;
            Kst[(c4*4+2)*68 + row] = kv.z;
            Kst[(c4*4+3)*68 + row] = kv.w;
            float4 vv = *(const float4*)(g_V + base + (size_t)(k0 + row)*stride + c4*4);
            *(float4*)(Vs + row*64 + c4*4) = vv;
        }
        __syncthreads();

        float S[8][4];
#pragma unroll
        for (int i = 0; i < 8; ++i)
#pragma unroll
            for (int j = 0; j < 4; ++j) S[i][j] = 0.f;
#pragma unroll 8
        for (int k = 0; k < 64; ++k) {
            float4 a0 = *(const float4*)(Qst + k*132 + ty*8);
            float4 a1 = *(const float4*)(Qst + k*132 + ty*8 + 4);
            float4 bv = *(const float4*)(Kst + k*68 + tx*4);
            float a[8] = {a0.x,a0.y,a0.z,a0.w,a1.x,a1.y,a1.z,a1.w};
#pragma unroll
            for (int i = 0; i < 8; ++i) {
                S[i][0] += a[i]*bv.x;
                S[i][1] += a[i]*bv.y;
                S[i][2] += a[i]*bv.z;
                S[i][3] += a[i]*bv.w;
            }
        }

#pragma unroll
        for (int i = 0; i < 8; ++i) {
            float mx = fmaxf(fmaxf(S[i][0], S[i][1]), fmaxf(S[i][2], S[i][3]));
#pragma unroll
            for (int w = 8; w > 0; w >>= 1)
                mx = fmaxf(mx, __shfl_xor_sync(0xffffffffu, mx, w));
            float mnew = fmaxf(m_i[i], mx);
            float corr = __expf(m_i[i] - mnew);
            m_i[i] = mnew;
            float rs = 0.f;
#pragma unroll
            for (int j = 0; j < 4; ++j) {
                float p = __expf(S[i][j] - mnew);
                S[i][j] = p;
                rs += p;
            }
#pragma unroll
            for (int w = 8; w > 0; w >>= 1)
                rs += __shfl_xor_sync(0xffffffffu, rs, w);
            l_i[i] = l_i[i]*corr + rs;
#pragma unroll
            for (int j = 0; j < 4; ++j) {
                O[i][j] *= corr;
                Pst[(tx*4+j)*132 + ty*8 + i] = S[i][j];
            }
        }
        __syncthreads();

#pragma unroll 8
        for (int k = 0; k < 64; ++k) {
            float4 p0 = *(const float4*)(Pst + k*132 + ty*8);
            float4 p1 = *(const float4*)(Pst + k*132 + ty*8 + 4);
            float4 vv = *(const float4*)(Vs + k*64 + tx*4);
            float p[8] = {p0.x,p0.y,p0.z,p0.w,p1.x,p1.y,p1.z,p1.w};
#pragma unroll
            for (int i = 0; i < 8; ++i) {
                O[i][0] += p[i]*vv.x;
                O[i][1] += p[i]*vv.y;
                O[i][2] += p[i]*vv.z;
                O[i][3] += p[i]*vv.w;
            }
        }
    }

#pragma unroll
    for (int i = 0; i < 8; ++i) {
        float inv = 1.0f / l_i[i];
        float4 o;
        o.x = O[i][0]*inv; o.y = O[i][1]*inv; o.z = O[i][2]*inv; o.w = O[i][3]*inv;
        int p = q0 + ty*8 + i;
        *(float4*)(g_O4 + base + (size_t)p*stride + tx*4) = o;
    }
}

// ---------------------------------------------------------------------------
// denom[b,c] = sum_n O4[b,n,c]; two-phase deterministic reduction
// ---------------------------------------------------------------------------
__global__ void colsum_part_kernel()
{
    int chunk = blockIdx.x;
    int bc    = blockIdx.y;
    int b  = bc / 3;
    int c  = (bc % 3)*256 + threadIdx.x;
    const float* p = g_O4 + ((size_t)b*NN + chunk*256)*EE + c;
    float s = 0.f;
#pragma unroll 8
    for (int n = 0; n < 256; ++n) {
        s += *p;
        p += EE;
    }
    g_part[chunk*(BB*EE) + b*EE + c] = s;
}

__global__ void colsum_reduce_kernel()
{
    int i = blockIdx.x*256 + threadIdx.x;
    float s = 0.f;
#pragma unroll
    for (int ch = 0; ch < 32; ++ch) s += g_part[ch*(BB*EE) + i];
    g_inv[i] = 1.0f / s;
}

// ---------------------------------------------------------------------------
extern "C" void kernel_launch(void* const* d_in, const int* in_sizes, int n_in,
                              void* d_out, int out_size)
{
    const float* query = (const float*)d_in[0];
    const float* key   = (const float*)d_in[1];
    const float* value = (const float*)d_in[2];
    const float* Wq = (const float*)d_in[3];
    const float* bq = (const float*)d_in[4];
    const float* Wk = (const float*)d_in[5];
    const float* bk = (const float*)d_in[6];
    const float* Wv = (const float*)d_in[7];
    const float* bv = (const float*)d_in[8];
    const float* Wo = (const float*)d_in[9];
    const float* bo = (const float*)d_in[10];
    float* out = (float*)d_out;

    float *pQ, *pK, *pV, *pO4, *pInv;
    cudaGetSymbolAddress((void**)&pQ,   g_Q);
    cudaGetSymbolAddress((void**)&pK,   g_K);
    cudaGetSymbolAddress((void**)&pV,   g_V);
    cudaGetSymbolAddress((void**)&pO4,  g_O4);
    cudaGetSymbolAddress((void**)&pInv, g_inv);

    cudaFuncSetAttribute(attn_kernel,
                         cudaFuncAttributeMaxDynamicSharedMemorySize,
                         ATTN_SMEM_BYTES);
    cudaFuncSetAttribute(gemm768_tc2_kernel,
                         cudaFuncAttributeMaxDynamicSharedMemorySize,
                         GEMM_SMEM_BYTES);

    dim3 gg(6, 128);

    // 1. zero scatter buffer
    zero_O4_kernel<<<12288, 256>>>();

    // 2. projections: split once, GEMM clean (Q pre-scaled by 1/8 after bias)
    splitW_kernel<<<576, 256>>>(Wq);
    splitA_kernel<<<12288, 256>>>(query, nullptr);
    gemm768_tc2_kernel<<<gg, 512, GEMM_SMEM_BYTES>>>(bq, 0.125f, pQ);

    splitW_kernel<<<576, 256>>>(Wk);
    splitA_kernel<<<12288, 256>>>(key, nullptr);
    gemm768_tc2_kernel<<<gg, 512, GEMM_SMEM_BYTES>>>(bk, 1.0f, pK);

    splitW_kernel<<<576, 256>>>(Wv);
    splitA_kernel<<<12288, 256>>>(value, nullptr);
    gemm768_tc2_kernel<<<gg, 512, GEMM_SMEM_BYTES>>>(bv, 1.0f, pV);

    // 3. dilated attention (56 instances x 16 q-tiles)
    attn_kernel<<<dim3(16, 56), 256, ATTN_SMEM_BYTES>>>();

    // 4. sequence-sum normalization factors
    colsum_part_kernel<<<dim3(32, 6), 256>>>();
    colsum_reduce_kernel<<<6, 256>>>();

    // 5. output projection; 1/denom folded into the A-split
    splitW_kernel<<<576, 256>>>(Wo);
    splitA_kernel<<<12288, 256>>>(pO4, pInv);
    gemm768_tc2_kernel<<<gg, 512, GEMM_SMEM_BYTES>>>(bo, 1.0f, out);
}

// round 11
// speedup vs baseline: 1.0505x; 1.0055x over previous
#include <cuda_runtime.h>
#include <cuda_bf16.h>
#include <math.h>

// Problem constants
#define BB 2
#define NN 8192
#define EE 768
#define HH 12
#define DD 64
#define MTOT (BB*NN)        // 16384

// Scratch (device globals: allocation-guard safe)
__device__ float g_Q[BB*NN*EE];
__device__ float g_K[BB*NN*EE];
__device__ float g_V[BB*NN*EE];
__device__ float g_O4[BB*NN*EE];
__device__ float g_part[32*BB*EE];
__device__ float g_inv[BB*EE];

// bf16 split planes (3-way exact decomposition), reused GEMM-to-GEMM
#define ASZ (MTOT*EE)
#define WSZ (EE*EE)
__device__ unsigned short g_sA[3*ASZ];   // ~75 MB
__device__ unsigned short g_sW[3*WSZ];   // ~3.5 MB

// ---------------------------------------------------------------------------
__global__ void zero_O4_kernel() {
    size_t i = (size_t)blockIdx.x * blockDim.x + threadIdx.x;
    ((float4*)g_O4)[i] = make_float4(0.f, 0.f, 0.f, 0.f);
}

// ---------------------------------------------------------------------------
// bf16 3-way exact split helpers
// ---------------------------------------------------------------------------
__device__ __forceinline__ unsigned short bfr(float x) {
    __nv_bfloat16 h = __float2bfloat16_rn(x);
    return *(unsigned short*)&h;
}
__device__ __forceinline__ float bff(unsigned short u) {
    __nv_bfloat16 h = *(__nv_bfloat16*)&u;
    return __bfloat162float(h);
}
__device__ __forceinline__ void split3(float x, unsigned short &a, unsigned short &b, unsigned short &c) {
    a = bfr(x);          float r1 = x - bff(a);
    b = bfr(r1);         float r2 = r1 - bff(b);
    c = bfr(r2);
}

// Split A[16384,768] (optionally scaled per (b,k) by colscale) into 3 planes.
__global__ void splitA_kernel(const float* __restrict__ A,
                              const float* __restrict__ colscale) {
    int i = blockIdx.x*256 + threadIdx.x;          // float4 index, 3145728 total
    float4 av = ((const float4*)A)[i];
    if (colscale) {
        int kq = i % 192;
        int m  = i / 192;
        float4 cs = ((const float4*)colscale)[(m >> 13)*192 + kq];
        av.x *= cs.x; av.y *= cs.y; av.z *= cs.z; av.w *= cs.w;
    }
    ushort4 sa, sb, sc;
    split3(av.x, sa.x, sb.x, sc.x); split3(av.y, sa.y, sb.y, sc.y);
    split3(av.z, sa.z, sb.z, sc.z); split3(av.w, sa.w, sb.w, sc.w);
    ((ushort4*)g_sA)[i]           = sa;
    ((ushort4*)(g_sA + ASZ))[i]   = sb;
    ((ushort4*)(g_sA + 2*ASZ))[i] = sc;
}

// Split W[768,768] into 3 planes.
__global__ void splitW_kernel(const float* __restrict__ W) {
    int i = blockIdx.x*256 + threadIdx.x;          // float4 index, 147456 total
    float4 wv = ((const float4*)W)[i];
    ushort4 sa, sb, sc;
    split3(wv.x, sa.x, sb.x, sc.x); split3(wv.y, sa.y, sb.y, sc.y);
    split3(wv.z, sa.z, sb.z, sc.z); split3(wv.w, sa.w, sb.w, sc.w);
    ((ushort4*)g_sW)[i]           = sa;
    ((ushort4*)(g_sW + WSZ))[i]   = sb;
    ((ushort4*)(g_sW + 2*WSZ))[i] = sc;
}

// ---------------------------------------------------------------------------
// bf16x6 tensor-core GEMM, precomputed splits, double-buffered, 512 threads.
// CTA 128x128, K-block 32, 16 warps (4Mx4N), warp tile 32x32, m16n8k16 MMA.
// Product-major issue order (breaks accumulator RAW chains); per-accumulator
// product order preserved (bb,ca,ac,ba,ab,aa) -> bit-identical numerics.
// ---------------------------------------------------------------------------
#define BLDA 40                    // smem row stride in bf16 (80B)
#define SPL  (128*BLDA)            // ushorts per plane buffer
#define SPLB (SPL*2u)              // bytes per plane buffer (10240)
#define STG  (6*SPL)               // ushorts per stage (6 planes)
#define STGB (6*SPLB)              // bytes per stage
#define GEMM_SMEM_BYTES (2*STGB)   // 122880

__device__ __forceinline__ void mma_bf16(float* acc, const unsigned* a, unsigned b0, unsigned b1) {
    asm volatile(
        "mma.sync.aligned.m16n8k16.row.col.f32.bf16.bf16.f32 "
        "{%0,%1,%2,%3}, {%4,%5,%6,%7}, {%8,%9}, {%0,%1,%2,%3};"
        : "+f"(acc[0]), "+f"(acc[1]), "+f"(acc[2]), "+f"(acc[3])
        : "r"(a[0]), "r"(a[1]), "r"(a[2]), "r"(a[3]), "r"(b0), "r"(b1));
}
__device__ __forceinline__ void mma_bf16_z(float* d, const unsigned* a, unsigned b0, unsigned b1) {
    asm volatile(
        "mma.sync.aligned.m16n8k16.row.col.f32.bf16.bf16.f32 "
        "{%0,%1,%2,%3}, {%4,%5,%6,%7}, {%8,%9}, {%10,%11,%12,%13};"
        : "=f"(d[0]), "=f"(d[1]), "=f"(d[2]), "=f"(d[3])
        : "r"(a[0]), "r"(a[1]), "r"(a[2]), "r"(a[3]), "r"(b0), "r"(b1),
          "f"(0.f), "f"(0.f), "f"(0.f), "f"(0.f));
}
__device__ __forceinline__ void ldsm4(unsigned* d, unsigned addr) {
    asm volatile("ldmatrix.sync.aligned.m8n8.x4.shared.b16 {%0,%1,%2,%3}, [%4];"
                 : "=r"(d[0]), "=r"(d[1]), "=r"(d[2]), "=r"(d[3]) : "r"(addr));
}

__global__ __launch_bounds__(512) void gemm768_tc2_kernel(
    const float* __restrict__ bias, float alpha, float* __restrict__ C)
{
    extern __shared__ unsigned short smu[];

    const int tid  = threadIdx.x;
    const int lane = tid & 31;
    const int wid  = tid >> 5;     // 0..15
    const int warp_m = wid & 3;    // 4 warps along M (32 each)
    const int warp_n = wid >> 2;   // 4 warps along N (32 each)
    const int m0 = blockIdx.y * 128;
    const int n0 = blockIdx.x * 128;

    const int lrow = tid >> 2;     // 0..127
    const int lcol = tid & 3;      // uint4 (8 bf16) index along 32-wide k

    float acc[2][4][4];            // master accumulator (RN adds)
    float accm[2][4][4];           // per-K-block chain accumulator
#pragma unroll
    for (int mt = 0; mt < 2; ++mt)
#pragma unroll
        for (int nt = 0; nt < 4; ++nt)
#pragma unroll
            for (int r = 0; r < 4; ++r) acc[mt][nt][r] = 0.f;

    const unsigned smbase = (unsigned)__cvta_generic_to_shared(smu);
    const unsigned a_off = (unsigned)((warp_m*32 + (lane & 15))*80) + ((lane >> 4) << 4);
    const unsigned b_off = (unsigned)((warp_n*32 + (lane & 15))*80) + ((lane >> 4) << 4);

    // product order per accumulator: bb, ca, ac, ba, ab, aa (unchanged from R8-R10)
    const int SA[6] = {1, 2, 0, 1, 0, 0};
    const int SB[6] = {1, 0, 2, 0, 1, 0};

#define LOAD_STAGE(t, buf)                                                          \
    {                                                                               \
        const int kb_ = (t)*32;                                                     \
        unsigned short* dst_ = smu + (buf)*STG;                                     \
        _Pragma("unroll")                                                           \
        for (int pl = 0; pl < 3; ++pl) {                                            \
            *(uint4*)(dst_ + pl*SPL + lrow*BLDA + lcol*8) =                         \
                *(const uint4*)(g_sA + (size_t)pl*ASZ + (size_t)(m0 + lrow)*768 + kb_ + lcol*8); \
            *(uint4*)(dst_ + (3+pl)*SPL + lrow*BLDA + lcol*8) =                     \
                *(const uint4*)(g_sW + (size_t)pl*WSZ + (size_t)(n0 + lrow)*768 + kb_ + lcol*8); \
        }                                                                           \
    }

    LOAD_STAGE(0, 0);
    __syncthreads();

    for (int t = 0; t < 24; ++t) {
        const int buf = t & 1;
        if (t < 23) LOAD_STAGE(t + 1, buf ^ 1);

        const unsigned stg = smbase + (unsigned)buf*STGB;
#pragma unroll
        for (int ks = 0; ks < 2; ++ks) {
            unsigned af[2][3][4];
#pragma unroll
            for (int mt = 0; mt < 2; ++mt)
#pragma unroll
                for (int s = 0; s < 3; ++s)
                    ldsm4(af[mt][s], stg + s*SPLB + a_off + mt*(16*80) + ks*32);

#pragma unroll
            for (int p = 0; p < 2; ++p) {       // two 16-row B groups (32 cols)
                unsigned bf[3][4];
#pragma unroll
                for (int s = 0; s < 3; ++s)
                    ldsm4(bf[s], stg + (3+s)*SPLB + b_off + p*(16*80) + ks*32);
                // product-major: one MMA per accumulator per product ->
                // same-accumulator spacing of 4 MMAs (RAW latency hidden)
#pragma unroll
                for (int prod = 0; prod < 6; ++prod) {
                    const int sa = SA[prod], sb = SB[prod];
#pragma unroll
                    for (int mt = 0; mt < 2; ++mt)
#pragma unroll
                        for (int h = 0; h < 2; ++h) {
                            float* ac = accm[mt][p*2 + h];
                            if (ks == 0 && prod == 0)
                                mma_bf16_z(ac, af[mt][sa], bf[sb][h], bf[sb][h+2]);
                            else
                                mma_bf16(ac, af[mt][sa], bf[sb][h], bf[sb][h+2]);
                        }
                }
            }
        }
        // RN respill
#pragma unroll
        for (int mt = 0; mt < 2; ++mt)
#pragma unroll
            for (int nt = 0; nt < 4; ++nt)
#pragma unroll
                for (int r = 0; r < 4; ++r)
                    acc[mt][nt][r] += accm[mt][nt][r];
        __syncthreads();
    }
#undef LOAD_STAGE

    // Epilogue: (acc + bias) * alpha, coalesced float2 stores
    const int r0 = lane >> 2;
    const int c0 = (lane & 3) * 2;
#pragma unroll
    for (int mt = 0; mt < 2; ++mt) {
#pragma unroll
        for (int nt = 0; nt < 4; ++nt) {
            int col = n0 + warp_n*32 + nt*8 + c0;
            float b0 = bias[col], b1 = bias[col + 1];
            int row_t = m0 + warp_m*32 + mt*16 + r0;
            float2 v0, v1;
            v0.x = (acc[mt][nt][0] + b0)*alpha; v0.y = (acc[mt][nt][1] + b1)*alpha;
            v1.x = (acc[mt][nt][2] + b0)*alpha; v1.y = (acc[mt][nt][3] + b1)*alpha;
            *(float2*)(C + (size_t)row_t*768 + col)       = v0;
            *(float2*)(C + (size_t)(row_t + 8)*768 + col) = v1;
        }
    }
}

// ---------------------------------------------------------------------------
// Dilated flash attention (scalar fp32 — best verified version).
// ---------------------------------------------------------------------------
#define ATTN_SMEM_FLOATS (64*132 + 64*68 + 64*64 + 64*132)
#define ATTN_SMEM_BYTES  (ATTN_SMEM_FLOATS*4)

__global__ __launch_bounds__(256, 2) void attn_kernel()
{
    extern __shared__ float sm[];
    float* Qst = sm;                      // [d=64][m=128] ld 132
    float* Kst = sm + 64*132;             // [d=64][n=64]  ld 68
    float* Vs  = Kst + 64*68;             // [k=64][d=64]  ld 64
    float* Pst = Vs + 64*64;              // [k=64][m=128] ld 132

    const int tid = threadIdx.x;
    const int tx = tid & 15, ty = tid >> 4;

    const int inst = blockIdx.y;
    int grp, b, seg, hl;
    if (inst < 32)      { grp = 0; b = inst >> 4;        seg = (inst >> 2) & 3; hl = inst & 3; }
    else if (inst < 48) { int r = inst - 32; grp = 1; b = r >> 3; seg = (r >> 2) & 1; hl = r & 3; }
    else                { int r = inst - 48; grp = 2; b = r >> 2; seg = 0;            hl = r & 3; }
    const int rate = 1 << grp;
    const int slen = 2048 << grp;
    const int off  = grp;
    const int head = grp*4 + hl;
    const int q0   = blockIdx.x * 128;

    const size_t base = (size_t)b*NN*EE + (size_t)(seg*slen + off)*EE + head*DD;
    const int stride = rate * EE;

#pragma unroll
    for (int l = 0; l < 8; ++l) {
        int idx = tid + l*256;
        int row = idx >> 4;
        int c4  = idx & 15;
        float4 v = *(const float4*)(g_Q + base + (size_t)(q0 + row)*stride + c4*4);
        Qst[(c4*4+0)*132 + row] = v.x;
        Qst[(c4*4+1)*132 + row] = v.y;
        Qst[(c4*4+2)*132 + row] = v.z;
        Qst[(c4*4+3)*132 + row] = v.w;
    }

    float m_i[8], l_i[8], O[8][4];
#pragma unroll
    for (int i = 0; i < 8; ++i) {
        m_i[i] = -1e30f; l_i[i] = 0.f;
#pragma unroll
        for (int j = 0; j < 4; ++j) O[i][j] = 0.f;
    }

    for (int kt = 0; kt < 32; ++kt) {
        const int k0 = kt * 64;
        __syncthreads();
#pragma unroll
        for (int l = 0; l < 4; ++l) {
            int idx = tid + l*256;
            int row = idx >> 4;
            int c4  = idx & 15;
            float4 kv = *(const float4*)(g_K + base + (size_t)(k0 + row)*stride + c4*4);
            Kst[(c4*4+0)*68 + row] = kv.x;
            Kst[(c4*4+1)*68 + row] = kv.y;
            Kst[(c4*4+2)*68 + row] = kv.z;
            Kst[(c4*4+3)*68 + row] = kv.w;
            float4 vv = *(const float4*)(g_V + base + (size_t)(k0 + row)*stride + c4*4);
            *(float4*)(Vs + row*64 + c4*4) = vv;
        }
        __syncthreads();

        float S[8][4];
#pragma unroll
        for (int i = 0; i < 8; ++i)
#pragma unroll
            for (int j = 0; j < 4; ++j) S[i][j] = 0.f;
#pragma unroll 8
        for (int k = 0; k < 64; ++k) {
            float4 a0 = *(const float4*)(Qst + k*132 + ty*8);
            float4 a1 = *(const float4*)(Qst + k*132 + ty*8 + 4);
            float4 bv = *(const float4*)(Kst + k*68 + tx*4);
            float a[8] = {a0.x,a0.y,a0.z,a0.w,a1.x,a1.y,a1.z,a1.w};
#pragma unroll
            for (int i = 0; i < 8; ++i) {
                S[i][0] += a[i]*bv.x;
                S[i][1] += a[i]*bv.y;
                S[i][2] += a[i]*bv.z;
                S[i][3] += a[i]*bv.w;
            }
        }

#pragma unroll
        for (int i = 0; i < 8; ++i) {
            float mx = fmaxf(fmaxf(S[i][0], S[i][1]), fmaxf(S[i][2], S[i][3]));
#pragma unroll
            for (int w = 8; w > 0; w >>= 1)
                mx = fmaxf(mx, __shfl_xor_sync(0xffffffffu, mx, w));
            float mnew = fmaxf(m_i[i], mx);
            float corr = __expf(m_i[i] - mnew);
            m_i[i] = mnew;
            float rs = 0.f;
#pragma unroll
            for (int j = 0; j < 4; ++j) {
                float p = __expf(S[i][j] - mnew);
                S[i][j] = p;
                rs += p;
            }
#pragma unroll
            for (int w = 8; w > 0; w >>= 1)
                rs += __shfl_xor_sync(0xffffffffu, rs, w);
            l_i[i] = l_i[i]*corr + rs;
#pragma unroll
            for (int j = 0; j < 4; ++j) {
                O[i][j] *= corr;
                Pst[(tx*4+j)*132 + ty*8 + i] = S[i][j];
            }
        }
        __syncthreads();

#pragma unroll 8
        for (int k = 0; k < 64; ++k) {
            float4 p0 = *(const float4*)(Pst + k*132 + ty*8);
            float4 p1 = *(const float4*)(Pst + k*132 + ty*8 + 4);
            float4 vv = *(const float4*)(Vs + k*64 + tx*4);
            float p[8] = {p0.x,p0.y,p0.z,p0.w,p1.x,p1.y,p1.z,p1.w};
#pragma unroll
            for (int i = 0; i < 8; ++i) {
                O[i][0] += p[i]*vv.x;
                O[i][1] += p[i]*vv.y;
                O[i][2] += p[i]*vv.z;
                O[i][3] += p[i]*vv.w;
            }
        }
    }

#pragma unroll
    for (int i = 0; i < 8; ++i) {
        float inv = 1.0f / l_i[i];
        float4 o;
        o.x = O[i][0]*inv; o.y = O[i][1]*inv; o.z = O[i][2]*inv; o.w = O[i][3]*inv;
        int p = q0 + ty*8 + i;
        *(float4*)(g_O4 + base + (size_t)p*stride + tx*4) = o;
    }
}

// ---------------------------------------------------------------------------
// denom[b,c] = sum_n O4[b,n,c]; two-phase deterministic reduction
// ---------------------------------------------------------------------------
__global__ void colsum_part_kernel()
{
    int chunk = blockIdx.x;
    int bc    = blockIdx.y;
    int b  = bc / 3;
    int c  = (bc % 3)*256 + threadIdx.x;
    const float* p = g_O4 + ((size_t)b*NN + chunk*256)*EE + c;
    float s = 0.f;
#pragma unroll 8
    for (int n = 0; n < 256; ++n) {
        s += *p;
        p += EE;
    }
    g_part[chunk*(BB*EE) + b*EE + c] = s;
}

__global__ void colsum_reduce_kernel()
{
    int i = blockIdx.x*256 + threadIdx.x;
    float s = 0.f;
#pragma unroll
    for (int ch = 0; ch < 32; ++ch) s += g_part[ch*(BB*EE) + i];
    g_inv[i] = 1.0f / s;
}

// ---------------------------------------------------------------------------
extern "C" void kernel_launch(void* const* d_in, const int* in_sizes, int n_in,
                              void* d_out, int out_size)
{
    const float* query = (const float*)d_in[0];
    const float* key   = (const float*)d_in[1];
    const float* value = (const float*)d_in[2];
    const float* Wq = (const float*)d_in[3];
    const float* bq = (const float*)d_in[4];
    const float* Wk = (const float*)d_in[5];
    const float* bk = (const float*)d_in[6];
    const float* Wv = (const float*)d_in[7];
    const float* bv = (const float*)d_in[8];
    const float* Wo = (const float*)d_in[9];
    const float* bo = (const float*)d_in[10];
    float* out = (float*)d_out;

    float *pQ, *pK, *pV, *pO4, *pInv;
    cudaGetSymbolAddress((void**)&pQ,   g_Q);
    cudaGetSymbolAddress((void**)&pK,   g_K);
    cudaGetSymbolAddress((void**)&pV,   g_V);
    cudaGetSymbolAddress((void**)&pO4,  g_O4);
    cudaGetSymbolAddress((void**)&pInv, g_inv);

    cudaFuncSetAttribute(attn_kernel,
                         cudaFuncAttributeMaxDynamicSharedMemorySize,
                         ATTN_SMEM_BYTES);
    cudaFuncSetAttribute(gemm768_tc2_kernel,
                         cudaFuncAttributeMaxDynamicSharedMemorySize,
                         GEMM_SMEM_BYTES);

    dim3 gg(6, 128);

    // 1. zero scatter buffer
    zero_O4_kernel<<<12288, 256>>>();

    // 2. projections: split once, GEMM clean (Q pre-scaled by 1/8 after bias)
    splitW_kernel<<<576, 256>>>(Wq);
    splitA_kernel<<<12288, 256>>>(query, nullptr);
    gemm768_tc2_kernel<<<gg, 512, GEMM_SMEM_BYTES>>>(bq, 0.125f, pQ);

    splitW_kernel<<<576, 256>>>(Wk);
    splitA_kernel<<<12288, 256>>>(key, nullptr);
    gemm768_tc2_kernel<<<gg, 512, GEMM_SMEM_BYTES>>>(bk, 1.0f, pK);

    splitW_kernel<<<576, 256>>>(Wv);
    splitA_kernel<<<12288, 256>>>(value, nullptr);
    gemm768_tc2_kernel<<<gg, 512, GEMM_SMEM_BYTES>>>(bv, 1.0f, pV);

    // 3. dilated attention (56 instances x 16 q-tiles)
    attn_kernel<<<dim3(16, 56), 256, ATTN_SMEM_BYTES>>>();

    // 4. sequence-sum normalization factors
    colsum_part_kernel<<<dim3(32, 6), 256>>>();
    colsum_reduce_kernel<<<6, 256>>>();

    // 5. output projection; 1/denom folded into the A-split
    splitW_kernel<<<576, 256>>>(Wo);
    splitA_kernel<<<12288, 256>>>(pO4, pInv);
    gemm768_tc2_kernel<<<gg, 512, GEMM_SMEM_BYTES>>>(bo, 1.0f, out);
}

// round 13
// speedup vs baseline: 1.3340x; 1.2699x over previous
#include <cuda_runtime.h>
#include <cuda_fp16.h>
#include <math.h>
#include <stdint.h>

// Problem constants
#define BB 2
#define NN 8192
#define EE 768
#define HH 12
#define DD 64
#define MTOT (BB*NN)        // 16384

// Scratch (device globals: allocation-guard safe)
__device__ float g_Q[BB*NN*EE];
__device__ float g_K[BB*NN*EE];
__device__ float g_V[BB*NN*EE];
__device__ float g_O4[BB*NN*EE];
__device__ float g_part[32*BB*EE];
__device__ float g_inv[BB*EE];

// fp16 split planes (2-way Markidis decomposition), reused GEMM-to-GEMM
#define ASZ (MTOT*EE)
#define WSZ (EE*EE)
__device__ unsigned short g_sA[2*ASZ];   // ~50 MB
__device__ unsigned short g_sW[2*WSZ];   // ~2.3 MB

// ---------------------------------------------------------------------------
__global__ void zero_O4_kernel() {
    size_t i = (size_t)blockIdx.x * blockDim.x + threadIdx.x;
    ((float4*)g_O4)[i] = make_float4(0.f, 0.f, 0.f, 0.f);
}

// ---------------------------------------------------------------------------
// fp16 2-way split helpers: x ~ a + b, residual ~2^-24 relative
// ---------------------------------------------------------------------------
__device__ __forceinline__ void split2(float x, unsigned short &a, unsigned short &b) {
    __half ha = __float2half_rn(x);
    float r1 = x - __half2float(ha);
    __half hb = __float2half_rn(r1);
    a = __half_as_ushort(ha);
    b = __half_as_ushort(hb);
}

// Split A[16384,768] (optionally scaled per (b,k) by colscale) into 2 planes.
__global__ void splitA_kernel(const float* __restrict__ A,
                              const float* __restrict__ colscale) {
    int i = blockIdx.x*256 + threadIdx.x;          // float4 index
    float4 av = ((const float4*)A)[i];
    if (colscale) {
        int kq = i % 192;
        int m  = i / 192;
        float4 cs = ((const float4*)colscale)[(m >> 13)*192 + kq];
        av.x *= cs.x; av.y *= cs.y; av.z *= cs.z; av.w *= cs.w;
    }
    ushort4 sa, sb;
    split2(av.x, sa.x, sb.x); split2(av.y, sa.y, sb.y);
    split2(av.z, sa.z, sb.z); split2(av.w, sa.w, sb.w);
    ((ushort4*)g_sA)[i]         = sa;
    ((ushort4*)(g_sA + ASZ))[i] = sb;
}

__global__ void splitW_kernel(const float* __restrict__ W) {
    int i = blockIdx.x*256 + threadIdx.x;
    float4 wv = ((const float4*)W)[i];
    ushort4 sa, sb;
    split2(wv.x, sa.x, sb.x); split2(wv.y, sa.y, sb.y);
    split2(wv.z, sa.z, sb.z); split2(wv.w, sa.w, sb.w);
    ((ushort4*)g_sW)[i]         = sa;
    ((ushort4*)(g_sW + WSZ))[i] = sb;
}

// ---------------------------------------------------------------------------
// fp16x3 tensor-core GEMM (Markidis: aa + ab + ba), precomputed splits,
// double-buffered, 512 threads. CTA 128x128, K-block 32, 16 warps (4Mx4N),
// warp tile 32x32, m16n8k16 f16 MMA, per-K-block chain restart + RN respill.
// Epilogue: C = (acc*s1 + bias)*s2.
// ---------------------------------------------------------------------------
#define BLDA 40                    // smem row stride in halfs (80B)
#define SPL  (128*BLDA)            // ushorts per plane buffer
#define SPLB (SPL*2u)              // bytes per plane buffer (10240)
#define STG  (4*SPL)               // ushorts per stage (A-a, A-b, W-a, W-b)
#define STGB (4*SPLB)              // bytes per stage (40960)
#define GEMM_SMEM_BYTES (2*STGB)   // 81920

__device__ __forceinline__ void mma_fp16(float* acc, const unsigned* a, unsigned b0, unsigned b1) {
    asm volatile(
        "mma.sync.aligned.m16n8k16.row.col.f32.f16.f16.f32 "
        "{%0,%1,%2,%3}, {%4,%5,%6,%7}, {%8,%9}, {%0,%1,%2,%3};"
        : "+f"(acc[0]), "+f"(acc[1]), "+f"(acc[2]), "+f"(acc[3])
        : "r"(a[0]), "r"(a[1]), "r"(a[2]), "r"(a[3]), "r"(b0), "r"(b1));
}
__device__ __forceinline__ void mma_fp16_z(float* d, const unsigned* a, unsigned b0, unsigned b1) {
    asm volatile(
        "mma.sync.aligned.m16n8k16.row.col.f32.f16.f16.f32 "
        "{%0,%1,%2,%3}, {%4,%5,%6,%7}, {%8,%9}, {%10,%11,%12,%13};"
        : "=f"(d[0]), "=f"(d[1]), "=f"(d[2]), "=f"(d[3])
        : "r"(a[0]), "r"(a[1]), "r"(a[2]), "r"(a[3]), "r"(b0), "r"(b1),
          "f"(0.f), "f"(0.f), "f"(0.f), "f"(0.f));
}
__device__ __forceinline__ void ldsm4(unsigned* d, unsigned addr) {
    asm volatile("ldmatrix.sync.aligned.m8n8.x4.shared.b16 {%0,%1,%2,%3}, [%4];"
                 : "=r"(d[0]), "=r"(d[1]), "=r"(d[2]), "=r"(d[3]) : "r"(addr));
}

__global__ __launch_bounds__(512) void gemm768_tc2_kernel(
    const float* __restrict__ bias, float s1, float s2, float* __restrict__ C)
{
    extern __shared__ unsigned short smu[];

    const int tid  = threadIdx.x;
    const int lane = tid & 31;
    const int wid  = tid >> 5;     // 0..15
    const int warp_m = wid & 3;    // 4 warps along M (32 each)
    const int warp_n = wid >> 2;   // 4 warps along N (32 each)
    const int m0 = blockIdx.y * 128;
    const int n0 = blockIdx.x * 128;

    const int lrow = tid >> 2;     // 0..127
    const int lcol = tid & 3;      // uint4 (8 halfs) index along 32-wide k

    float acc[2][4][4];            // master accumulator (RN adds)
    float accm[2][4][4];           // per-K-block chain accumulator
#pragma unroll
    for (int mt = 0; mt < 2; ++mt)
#pragma unroll
        for (int nt = 0; nt < 4; ++nt)
#pragma unroll
            for (int r = 0; r < 4; ++r) acc[mt][nt][r] = 0.f;

    const unsigned smbase = (unsigned)__cvta_generic_to_shared(smu);
    const unsigned a_off = (unsigned)((warp_m*32 + (lane & 15))*80) + ((lane >> 4) << 4);
    const unsigned b_off = (unsigned)((warp_n*32 + (lane & 15))*80) + ((lane >> 4) << 4);

    // product order per accumulator: ab, ba, aa (ascending magnitude last-dominant)
    const int SA[3] = {0, 1, 0};
    const int SB[3] = {1, 0, 0};

#define LOAD_STAGE(t, buf)                                                          \
    {                                                                               \
        const int kb_ = (t)*32;                                                     \
        unsigned short* dst_ = smu + (buf)*STG;                                     \
        _Pragma("unroll")                                                           \
        for (int pl = 0; pl < 2; ++pl) {                                            \
            *(uint4*)(dst_ + pl*SPL + lrow*BLDA + lcol*8) =                         \
                *(const uint4*)(g_sA + (size_t)pl*ASZ + (size_t)(m0 + lrow)*768 + kb_ + lcol*8); \
            *(uint4*)(dst_ + (2+pl)*SPL + lrow*BLDA + lcol*8) =                     \
                *(const uint4*)(g_sW + (size_t)pl*WSZ + (size_t)(n0 + lrow)*768 + kb_ + lcol*8); \
        }                                                                           \
    }

    LOAD_STAGE(0, 0);
    __syncthreads();

    for (int t = 0; t < 24; ++t) {
        const int buf = t & 1;
        if (t < 23) LOAD_STAGE(t + 1, buf ^ 1);

        const unsigned stg = smbase + (unsigned)buf*STGB;
#pragma unroll
        for (int ks = 0; ks < 2; ++ks) {
            unsigned af[2][2][4];
#pragma unroll
            for (int mt = 0; mt < 2; ++mt)
#pragma unroll
                for (int s = 0; s < 2; ++s)
                    ldsm4(af[mt][s], stg + s*SPLB + a_off + mt*(16*80) + ks*32);

#pragma unroll
            for (int p = 0; p < 2; ++p) {       // two 16-row B groups (32 cols)
                unsigned bf[2][4];
#pragma unroll
                for (int s = 0; s < 2; ++s)
                    ldsm4(bf[s], stg + (2+s)*SPLB + b_off + p*(16*80) + ks*32);
                // product-major: one MMA per accumulator per product
#pragma unroll
                for (int prod = 0; prod < 3; ++prod) {
                    const int sa = SA[prod], sb = SB[prod];
#pragma unroll
                    for (int mt = 0; mt < 2; ++mt)
#pragma unroll
                        for (int h = 0; h < 2; ++h) {
                            float* ac = accm[mt][p*2 + h];
                            if (ks == 0 && prod == 0)
                                mma_fp16_z(ac, af[mt][sa], bf[sb][h], bf[sb][h+2]);
                            else
                                mma_fp16(ac, af[mt][sa], bf[sb][h], bf[sb][h+2]);
                        }
                }
            }
        }
        // RN respill
#pragma unroll
        for (int mt = 0; mt < 2; ++mt)
#pragma unroll
            for (int nt = 0; nt < 4; ++nt)
#pragma unroll
                for (int r = 0; r < 4; ++r)
                    acc[mt][nt][r] += accm[mt][nt][r];
        __syncthreads();
    }
#undef LOAD_STAGE

    // Epilogue: C = (acc*s1 + bias)*s2, coalesced float2 stores
    const int r0 = lane >> 2;
    const int c0 = (lane & 3) * 2;
#pragma unroll
    for (int mt = 0; mt < 2; ++mt) {
#pragma unroll
        for (int nt = 0; nt < 4; ++nt) {
            int col = n0 + warp_n*32 + nt*8 + c0;
            float b0 = bias[col], b1 = bias[col + 1];
            int row_t = m0 + warp_m*32 + mt*16 + r0;
            float2 v0, v1;
            v0.x = (acc[mt][nt][0]*s1 + b0)*s2; v0.y = (acc[mt][nt][1]*s1 + b1)*s2;
            v1.x = (acc[mt][nt][2]*s1 + b0)*s2; v1.y = (acc[mt][nt][3]*s1 + b1)*s2;
            *(float2*)(C + (size_t)row_t*768 + col)       = v0;
            *(float2*)(C + (size_t)(row_t + 8)*768 + col) = v1;
        }
    }
}

// ---------------------------------------------------------------------------
// Dilated flash attention (scalar fp32 — best verified version).
// ---------------------------------------------------------------------------
#define ATTN_SMEM_FLOATS (64*132 + 64*68 + 64*64 + 64*132)
#define ATTN_SMEM_BYTES  (ATTN_SMEM_FLOATS*4)

__global__ __launch_bounds__(256, 2) void attn_kernel()
{
    extern __shared__ float sm[];
    float* Qst = sm;                      // [d=64][m=128] ld 132
    float* Kst = sm + 64*132;             // [d=64][n=64]  ld 68
    float* Vs  = Kst + 64*68;             // [k=64][d=64]  ld 64
    float* Pst = Vs + 64*64;              // [k=64][m=128] ld 132

    const int tid = threadIdx.x;
    const int tx = tid & 15, ty = tid >> 4;

    const int inst = blockIdx.y;
    int grp, b, seg, hl;
    if (inst < 32)      { grp = 0; b = inst >> 4;        seg = (inst >> 2) & 3; hl = inst & 3; }
    else if (inst < 48) { int r = inst - 32; grp = 1; b = r >> 3; seg = (r >> 2) & 1; hl = r & 3; }
    else                { int r = inst - 48; grp = 2; b = r >> 2; seg = 0;            hl = r & 3; }
    const int rate = 1 << grp;
    const int slen = 2048 << grp;
    const int off  = grp;
    const int head = grp*4 + hl;
    const int q0   = blockIdx.x * 128;

    const size_t base = (size_t)b*NN*EE + (size_t)(seg*slen + off)*EE + head*DD;
    const int stride = rate * EE;

#pragma unroll
    for (int l = 0; l < 8; ++l) {
        int idx = tid + l*256;
        int row = idx >> 4;
        int c4  = idx & 15;
        float4 v = *(const float4*)(g_Q + base + (size_t)(q0 + row)*stride + c4*4);
        Qst[(c4*4+0)*132 + row] = v.x;
        Qst[(c4*4+1)*132 + row] = v.y;
        Qst[(c4*4+2)*132 + row] = v.z;
        Qst[(c4*4+3)*132 + row] = v.w;
    }

    float m_i[8], l_i[8], O[8][4];
#pragma unroll
    for (int i = 0; i < 8; ++i) {
        m_i[i] = -1e30f; l_i[i] = 0.f;
#pragma unroll
        for (int j = 0; j < 4; ++j) O[i][j] = 0.f;
    }

    for (int kt = 0; kt < 32; ++kt) {
        const int k0 = kt * 64;
        __syncthreads();
#pragma unroll
        for (int l = 0; l < 4; ++l) {
            int idx = tid + l*256;
            int row = idx >> 4;
            int c4  = idx & 15;
            float4 kv = *(const float4*)(g_K + base + (size_t)(k0 + row)*stride + c4*4);
            Kst[(c4*4+0)*68 + row] = kv.x;
            Kst[(c4*4+1)*68 + row] = kv.y;
            Kst[(c4*4+2)*68 + row] = kv.z;
            Kst[(c4*4+3)*68 + row] = kv.w;
            float4 vv = *(const float4*)(g_V + base + (size_t)(k0 + row)*stride + c4*4);
            *(float4*)(Vs + row*64 + c4*4) = vv;
        }
        __syncthreads();

        float S[8][4];
#pragma unroll
        for (int i = 0; i < 8; ++i)
#pragma unroll
            for (int j = 0; j < 4; ++j) S[i][j] = 0.f;
#pragma unroll 8
        for (int k = 0; k < 64; ++k) {
            float4 a0 = *(const float4*)(Qst + k*132 + ty*8);
            float4 a1 = *(const float4*)(Qst + k*132 + ty*8 + 4);
            float4 bv = *(const float4*)(Kst + k*68 + tx*4);
            float a[8] = {a0.x,a0.y,a0.z,a0.w,a1.x,a1.y,a1.z,a1.w};
#pragma unroll
            for (int i = 0; i < 8; ++i) {
                S[i][0] += a[i]*bv.x;
                S[i][1] += a[i]*bv.y;
                S[i][2] += a[i]*bv.z;
                S[i][3] += a[i]*bv.w;
            }
        }

#pragma unroll
        for (int i = 0; i < 8; ++i) {
            float mx = fmaxf(fmaxf(S[i][0], S[i][1]), fmaxf(S[i][2], S[i][3]));
#pragma unroll
            for (int w = 8; w > 0; w >>= 1)
                mx = fmaxf(mx, __shfl_xor_sync(0xffffffffu, mx, w));
            float mnew = fmaxf(m_i[i], mx);
            float corr = __expf(m_i[i] - mnew);
            m_i[i] = mnew;
            float rs = 0.f;
#pragma unroll
            for (int j = 0; j < 4; ++j) {
                float p = __expf(S[i][j] - mnew);
                S[i][j] = p;
                rs += p;
            }
#pragma unroll
            for (int w = 8; w > 0; w >>= 1)
                rs += __shfl_xor_sync(0xffffffffu, rs, w);
            l_i[i] = l_i[i]*corr + rs;
#pragma unroll
            for (int j = 0; j < 4; ++j) {
                O[i][j] *= corr;
                Pst[(tx*4+j)*132 + ty*8 + i] = S[i][j];
            }
        }
        __syncthreads();

#pragma unroll 8
        for (int k = 0; k < 64; ++k) {
            float4 p0 = *(const float4*)(Pst + k*132 + ty*8);
            float4 p1 = *(const float4*)(Pst + k*132 + ty*8 + 4);
            float4 vv = *(const float4*)(Vs + k*64 + tx*4);
            float p[8] = {p0.x,p0.y,p0.z,p0.w,p1.x,p1.y,p1.z,p1.w};
#pragma unroll
            for (int i = 0; i < 8; ++i) {
                O[i][0] += p[i]*vv.x;
                O[i][1] += p[i]*vv.y;
                O[i][2] += p[i]*vv.z;
                O[i][3] += p[i]*vv.w;
            }
        }
    }

#pragma unroll
    for (int i = 0; i < 8; ++i) {
        float inv = 1.0f / l_i[i];
        float4 o;
        o.x = O[i][0]*inv; o.y = O[i][1]*inv; o.z = O[i][2]*inv; o.w = O[i][3]*inv;
        int p = q0 + ty*8 + i;
        *(float4*)(g_O4 + base + (size_t)p*stride + tx*4) = o;
    }
}

// ---------------------------------------------------------------------------
// denom[b,c] = sum_n O4[b,n,c]; two-phase deterministic reduction.
// g_inv = 64/denom (the 64x keeps the O4 split planes in fp16 normal range;
// the matching 1/64 is applied via s1 in the output-projection GEMM).
// ---------------------------------------------------------------------------
__global__ void colsum_part_kernel()
{
    int chunk = blockIdx.x;
    int bc    = blockIdx.y;
    int b  = bc / 3;
    int c  = (bc % 3)*256 + threadIdx.x;
    const float* p = g_O4 + ((size_t)b*NN + chunk*256)*EE + c;
    float s = 0.f;
#pragma unroll 8
    for (int n = 0; n < 256; ++n) {
        s += *p;
        p += EE;
    }
    g_part[chunk*(BB*EE) + b*EE + c] = s;
}

__global__ void colsum_reduce_kernel()
{
    int i = blockIdx.x*256 + threadIdx.x;
    float s = 0.f;
#pragma unroll
    for (int ch = 0; ch < 32; ++ch) s += g_part[ch*(BB*EE) + i];
    g_inv[i] = 64.0f / s;
}

// ---------------------------------------------------------------------------
extern "C" void kernel_launch(void* const* d_in, const int* in_sizes, int n_in,
                              void* d_out, int out_size)
{
    const float* query = (const float*)d_in[0];
    const float* key   = (const float*)d_in[1];
    const float* value = (const float*)d_in[2];
    const float* Wq = (const float*)d_in[3];
    const float* bq = (const float*)d_in[4];
    const float* Wk = (const float*)d_in[5];
    const float* bk = (const float*)d_in[6];
    const float* Wv = (const float*)d_in[7];
    const float* bv = (const float*)d_in[8];
    const float* Wo = (const float*)d_in[9];
    const float* bo = (const float*)d_in[10];
    float* out = (float*)d_out;

    float *pQ, *pK, *pV, *pO4, *pInv;
    cudaGetSymbolAddress((void**)&pQ,   g_Q);
    cudaGetSymbolAddress((void**)&pK,   g_K);
    cudaGetSymbolAddress((void**)&pV,   g_V);
    cudaGetSymbolAddress((void**)&pO4,  g_O4);
    cudaGetSymbolAddress((void**)&pInv, g_inv);

    cudaFuncSetAttribute(attn_kernel,
                         cudaFuncAttributeMaxDynamicSharedMemorySize,
                         ATTN_SMEM_BYTES);
    cudaFuncSetAttribute(gemm768_tc2_kernel,
                         cudaFuncAttributeMaxDynamicSharedMemorySize,
                         GEMM_SMEM_BYTES);

    dim3 gg(6, 128);

    // 1. zero scatter buffer
    zero_O4_kernel<<<12288, 256>>>();

    // 2. projections: fp16x2 split once, fp16x3 GEMM
    //    (Q: (acc + bias)*0.125 via s1=1, s2=0.125)
    splitW_kernel<<<576, 256>>>(Wq);
    splitA_kernel<<<12288, 256>>>(query, nullptr);
    gemm768_tc2_kernel<<<gg, 512, GEMM_SMEM_BYTES>>>(bq, 1.0f, 0.125f, pQ);

    splitW_kernel<<<576, 256>>>(Wk);
    splitA_kernel<<<12288, 256>>>(key, nullptr);
    gemm768_tc2_kernel<<<gg, 512, GEMM_SMEM_BYTES>>>(bk, 1.0f, 1.0f, pK);

    splitW_kernel<<<576, 256>>>(Wv);
    splitA_kernel<<<12288, 256>>>(value, nullptr);
    gemm768_tc2_kernel<<<gg, 512, GEMM_SMEM_BYTES>>>(bv, 1.0f, 1.0f, pV);

    // 3. dilated attention (56 instances x 16 q-tiles)
    attn_kernel<<<dim3(16, 56), 256, ATTN_SMEM_BYTES>>>();

    // 4. sequence-sum normalization factors (64/denom)
    colsum_part_kernel<<<dim3(32, 6), 256>>>();
    colsum_reduce_kernel<<<6, 256>>>();

    // 5. output projection; 64/denom folded into A-split, 1/64 via s1
    splitW_kernel<<<576, 256>>>(Wo);
    splitA_kernel<<<12288, 256>>>(pO4, pInv);
    gemm768_tc2_kernel<<<gg, 512, GEMM_SMEM_BYTES>>>(bo, 1.0f/64.0f, 1.0f, out);
}

// round 14
// speedup vs baseline: 1.9405x; 1.4546x over previous
#include <cuda_runtime.h>
#include <cuda_fp16.h>
#include <math.h>
#include <stdint.h>

// Problem constants
#define BB 2
#define NN 8192
#define EE 768
#define HH 12
#define DD 64
#define MTOT (BB*NN)        // 16384

// Scratch (device globals: allocation-guard safe)
__device__ float g_O4[BB*NN*EE];
__device__ float g_part[32*BB*EE];
__device__ float g_inv[BB*EE];

#define ASZ (MTOT*EE)
#define WSZ (EE*EE)
// GEMM operand split planes
__device__ unsigned short g_sA[2*ASZ];
__device__ unsigned short g_sW[2*WSZ];
// Q/K/V fp16 hi/lo planes (written by projection GEMM epilogues)
__device__ unsigned short g_pQh[ASZ], g_pQl[ASZ];
__device__ unsigned short g_pKh[ASZ], g_pKl[ASZ];
__device__ unsigned short g_pVh[ASZ], g_pVl[ASZ];

// ---------------------------------------------------------------------------
__global__ void zero_O4_kernel() {
    size_t i = (size_t)blockIdx.x * blockDim.x + threadIdx.x;
    ((float4*)g_O4)[i] = make_float4(0.f, 0.f, 0.f, 0.f);
}

// ---------------------------------------------------------------------------
// fp16 2-way split: x ~ a + b
// ---------------------------------------------------------------------------
__device__ __forceinline__ void split2(float x, unsigned short &a, unsigned short &b) {
    __half ha = __float2half_rn(x);
    float r1 = x - __half2float(ha);
    __half hb = __float2half_rn(r1);
    a = __half_as_ushort(ha);
    b = __half_as_ushort(hb);
}

__global__ void splitA_kernel(const float* __restrict__ A,
                              const float* __restrict__ colscale) {
    int i = blockIdx.x*256 + threadIdx.x;
    float4 av = ((const float4*)A)[i];
    if (colscale) {
        int kq = i % 192;
        int m  = i / 192;
        float4 cs = ((const float4*)colscale)[(m >> 13)*192 + kq];
        av.x *= cs.x; av.y *= cs.y; av.z *= cs.z; av.w *= cs.w;
    }
    ushort4 sa, sb;
    split2(av.x, sa.x, sb.x); split2(av.y, sa.y, sb.y);
    split2(av.z, sa.z, sb.z); split2(av.w, sa.w, sb.w);
    ((ushort4*)g_sA)[i]         = sa;
    ((ushort4*)(g_sA + ASZ))[i] = sb;
}

__global__ void splitW_kernel(const float* __restrict__ W) {
    int i = blockIdx.x*256 + threadIdx.x;
    float4 wv = ((const float4*)W)[i];
    ushort4 sa, sb;
    split2(wv.x, sa.x, sb.x); split2(wv.y, sa.y, sb.y);
    split2(wv.z, sa.z, sb.z); split2(wv.w, sa.w, sb.w);
    ((ushort4*)g_sW)[i]         = sa;
    ((ushort4*)(g_sW + WSZ))[i] = sb;
}

// ---------------------------------------------------------------------------
// MMA helpers
// ---------------------------------------------------------------------------
__device__ __forceinline__ void mma_fp16(float* acc, const unsigned* a, unsigned b0, unsigned b1) {
    asm volatile(
        "mma.sync.aligned.m16n8k16.row.col.f32.f16.f16.f32 "
        "{%0,%1,%2,%3}, {%4,%5,%6,%7}, {%8,%9}, {%0,%1,%2,%3};"
        : "+f"(acc[0]), "+f"(acc[1]), "+f"(acc[2]), "+f"(acc[3])
        : "r"(a[0]), "r"(a[1]), "r"(a[2]), "r"(a[3]), "r"(b0), "r"(b1));
}
__device__ __forceinline__ void mma_fp16_z(float* d, const unsigned* a, unsigned b0, unsigned b1) {
    asm volatile(
        "mma.sync.aligned.m16n8k16.row.col.f32.f16.f16.f32 "
        "{%0,%1,%2,%3}, {%4,%5,%6,%7}, {%8,%9}, {%10,%11,%12,%13};"
        : "=f"(d[0]), "=f"(d[1]), "=f"(d[2]), "=f"(d[3])
        : "r"(a[0]), "r"(a[1]), "r"(a[2]), "r"(a[3]), "r"(b0), "r"(b1),
          "f"(0.f), "f"(0.f), "f"(0.f), "f"(0.f));
}
__device__ __forceinline__ void ldsm4(unsigned* d, unsigned addr) {
    asm volatile("ldmatrix.sync.aligned.m8n8.x4.shared.b16 {%0,%1,%2,%3}, [%4];"
                 : "=r"(d[0]), "=r"(d[1]), "=r"(d[2]), "=r"(d[3]) : "r"(addr));
}
__device__ __forceinline__ void ldsm4t(unsigned* d, unsigned addr) {
    asm volatile("ldmatrix.sync.aligned.m8n8.x4.trans.shared.b16 {%0,%1,%2,%3}, [%4];"
                 : "=r"(d[0]), "=r"(d[1]), "=r"(d[2]), "=r"(d[3]) : "r"(addr));
}

// ---------------------------------------------------------------------------
// fp16x3 projection GEMM (validated R13).  Epilogue writes EITHER fp32 C OR
// fp16 hi/lo planes of (acc*s1 + bias)*s2.
// ---------------------------------------------------------------------------
#define BLDA 40
#define SPL  (128*BLDA)
#define SPLB (SPL*2u)
#define STG  (4*SPL)
#define STGB (4*SPLB)
#define GEMM_SMEM_BYTES (2*STGB)   // 81920

__global__ __launch_bounds__(512) void gemm768_tc2_kernel(
    const float* __restrict__ bias, float s1, float s2, float* __restrict__ C,
    unsigned short* __restrict__ outH, unsigned short* __restrict__ outL)
{
    extern __shared__ unsigned short smu[];

    const int tid  = threadIdx.x;
    const int lane = tid & 31;
    const int wid  = tid >> 5;
    const int warp_m = wid & 3;
    const int warp_n = wid >> 2;
    const int m0 = blockIdx.y * 128;
    const int n0 = blockIdx.x * 128;

    const int lrow = tid >> 2;
    const int lcol = tid & 3;

    float acc[2][4][4];
    float accm[2][4][4];
#pragma unroll
    for (int mt = 0; mt < 2; ++mt)
#pragma unroll
        for (int nt = 0; nt < 4; ++nt)
#pragma unroll
            for (int r = 0; r < 4; ++r) acc[mt][nt][r] = 0.f;

    const unsigned smbase = (unsigned)__cvta_generic_to_shared(smu);
    const unsigned a_off = (unsigned)((warp_m*32 + (lane & 15))*80) + ((lane >> 4) << 4);
    const unsigned b_off = (unsigned)((warp_n*32 + (lane & 15))*80) + ((lane >> 4) << 4);

    const int SA[3] = {0, 1, 0};
    const int SB[3] = {1, 0, 0};

#define LOAD_STAGE(t, buf)                                                          \
    {                                                                               \
        const int kb_ = (t)*32;                                                     \
        unsigned short* dst_ = smu + (buf)*STG;                                     \
        _Pragma("unroll")                                                           \
        for (int pl = 0; pl < 2; ++pl) {                                            \
            *(uint4*)(dst_ + pl*SPL + lrow*BLDA + lcol*8) =                         \
                *(const uint4*)(g_sA + (size_t)pl*ASZ + (size_t)(m0 + lrow)*768 + kb_ + lcol*8); \
            *(uint4*)(dst_ + (2+pl)*SPL + lrow*BLDA + lcol*8) =                     \
                *(const uint4*)(g_sW + (size_t)pl*WSZ + (size_t)(n0 + lrow)*768 + kb_ + lcol*8); \
        }                                                                           \
    }

    LOAD_STAGE(0, 0);
    __syncthreads();

    for (int t = 0; t < 24; ++t) {
        const int buf = t & 1;
        if (t < 23) LOAD_STAGE(t + 1, buf ^ 1);

        const unsigned stg = smbase + (unsigned)buf*STGB;
#pragma unroll
        for (int ks = 0; ks < 2; ++ks) {
            unsigned af[2][2][4];
#pragma unroll
            for (int mt = 0; mt < 2; ++mt)
#pragma unroll
                for (int s = 0; s < 2; ++s)
                    ldsm4(af[mt][s], stg + s*SPLB + a_off + mt*(16*80) + ks*32);

#pragma unroll
            for (int p = 0; p < 2; ++p) {
                unsigned bf[2][4];
#pragma unroll
                for (int s = 0; s < 2; ++s)
                    ldsm4(bf[s], stg + (2+s)*SPLB + b_off + p*(16*80) + ks*32);
#pragma unroll
                for (int prod = 0; prod < 3; ++prod) {
                    const int sa = SA[prod], sb = SB[prod];
#pragma unroll
                    for (int mt = 0; mt < 2; ++mt)
#pragma unroll
                        for (int h = 0; h < 2; ++h) {
                            float* ac = accm[mt][p*2 + h];
                            if (ks == 0 && prod == 0)
                                mma_fp16_z(ac, af[mt][sa], bf[sb][h], bf[sb][h+2]);
                            else
                                mma_fp16(ac, af[mt][sa], bf[sb][h], bf[sb][h+2]);
                        }
                }
            }
        }
#pragma unroll
        for (int mt = 0; mt < 2; ++mt)
#pragma unroll
            for (int nt = 0; nt < 4; ++nt)
#pragma unroll
                for (int r = 0; r < 4; ++r)
                    acc[mt][nt][r] += accm[mt][nt][r];
        __syncthreads();
    }
#undef LOAD_STAGE

    const int r0 = lane >> 2;
    const int c0 = (lane & 3) * 2;
#pragma unroll
    for (int mt = 0; mt < 2; ++mt) {
#pragma unroll
        for (int nt = 0; nt < 4; ++nt) {
            int col = n0 + warp_n*32 + nt*8 + c0;
            float b0 = bias[col], b1 = bias[col + 1];
            int row_t = m0 + warp_m*32 + mt*16 + r0;
            float v00 = (acc[mt][nt][0]*s1 + b0)*s2, v01 = (acc[mt][nt][1]*s1 + b1)*s2;
            float v10 = (acc[mt][nt][2]*s1 + b0)*s2, v11 = (acc[mt][nt][3]*s1 + b1)*s2;
            if (outH) {
                unsigned short h0,l0,h1,l1;
                split2(v00,h0,l0); split2(v01,h1,l1);
                *(unsigned*)(outH + (size_t)row_t*768 + col) = (unsigned)h0 | ((unsigned)h1<<16);
                *(unsigned*)(outL + (size_t)row_t*768 + col) = (unsigned)l0 | ((unsigned)l1<<16);
                split2(v10,h0,l0); split2(v11,h1,l1);
                *(unsigned*)(outH + (size_t)(row_t+8)*768 + col) = (unsigned)h0 | ((unsigned)h1<<16);
                *(unsigned*)(outL + (size_t)(row_t+8)*768 + col) = (unsigned)l0 | ((unsigned)l1<<16);
            } else {
                *(float2*)(C + (size_t)row_t*768 + col)       = make_float2(v00, v01);
                *(float2*)(C + (size_t)(row_t + 8)*768 + col) = make_float2(v10, v11);
            }
        }
    }
}

// ---------------------------------------------------------------------------
// fp16x3 MMA dilated flash attention.
// Block: 128 q-rows of one instance; 8 warps, each warp owns 16 q-rows.
// Per 64-key chunk: S = Q*K^T (3 products, chain restart), fp32 softmax,
// P split2 -> smem, O_chunk = P*V (3 products, restart), O = O*corr + O_chunk.
// smem halfs, row stride 72 (144B).
// ---------------------------------------------------------------------------
#define QH_B 0u
#define QL_B 18432u
#define KH_B 36864u
#define KL_B 46080u
#define VH_B 55296u
#define VL_B 64512u
#define PH_B 73728u
#define PL_B 92160u
#define ATTN_SMEM_BYTES 110592

__global__ __launch_bounds__(256) void attn_kernel()
{
    extern __shared__ unsigned short smh[];
    const int tid  = threadIdx.x;
    const int lane = tid & 31;
    const int warp = tid >> 5;          // 0..7

    const int inst = blockIdx.y;
    int grp, b, seg, hl;
    if (inst < 32)      { grp = 0; b = inst >> 4;        seg = (inst >> 2) & 3; hl = inst & 3; }
    else if (inst < 48) { int r = inst - 32; grp = 1; b = r >> 3; seg = (r >> 2) & 1; hl = r & 3; }
    else                { int r = inst - 48; grp = 2; b = r >> 2; seg = 0;            hl = r & 3; }
    const int rate = 1 << grp;
    const int slen = 2048 << grp;
    const int off  = grp;
    const int head = grp*4 + hl;
    const int q0   = blockIdx.x * 128;

    const size_t baseH = (size_t)b*NN*EE + (size_t)(seg*slen + off)*EE + head*DD;
    const int strideE = rate * EE;

    const unsigned smb = (unsigned)__cvta_generic_to_shared(smh);
    char* smc = (char*)smh;

    // Load Q tile (hi/lo planes) into smem
#pragma unroll
    for (int i = 0; i < 4; ++i) {
        int idx = tid + i*256;           // 1024 = 128 rows x 8 chunks
        int row = idx >> 3, c = idx & 7;
        size_t src = baseH + (size_t)(q0 + row)*strideE + c*8;
        *(uint4*)(smc + QH_B + row*144 + c*16) = *(const uint4*)(g_pQh + src);
        *(uint4*)(smc + QL_B + row*144 + c*16) = *(const uint4*)(g_pQl + src);
    }

    // ldsm base offsets
    const unsigned aQH = smb + QH_B + (unsigned)((warp*16 + (lane & 15))*144) + ((lane >> 4) << 4);
    const unsigned aQL = aQH + (QL_B - QH_B);
    const unsigned bKH = smb + KH_B + (unsigned)((lane & 15)*144) + ((lane >> 4) << 4);
    const unsigned bKL = bKH + (KL_B - KH_B);
    const unsigned aPH = smb + PH_B + (unsigned)((warp*16 + (lane & 15))*144) + ((lane >> 4) << 4);
    const unsigned aPL = aPH + (PL_B - PH_B);

    float O[8][4];
#pragma unroll
    for (int nt = 0; nt < 8; ++nt)
#pragma unroll
        for (int r = 0; r < 4; ++r) O[nt][r] = 0.f;
    float mi0 = -1e30f, mi1 = -1e30f, li0 = 0.f, li1 = 0.f;

    const int r0 = lane >> 2;
    const int c0 = (lane & 3)*2;

    for (int kt = 0; kt < 32; ++kt) {
        const int k0 = kt*64;
        __syncthreads();
        // load K,V chunk (hi/lo)
#pragma unroll
        for (int i = 0; i < 8; ++i) {
            int idx = tid + i*256;       // 2048 = 4 arrays x 64 rows x 8 chunks
            int arr = idx >> 9;
            int rem = idx & 511;
            int row = rem >> 3, c = rem & 7;
            size_t src = baseH + (size_t)(k0 + row)*strideE + c*8;
            const unsigned short* sp = (arr == 0) ? g_pKh : (arr == 1) ? g_pKl
                                     : (arr == 2) ? g_pVh : g_pVl;
            unsigned dst = (arr == 0) ? KH_B : (arr == 1) ? KL_B
                         : (arr == 2) ? VH_B : VL_B;
            *(uint4*)(smc + dst + row*144 + c*16) = *(const uint4*)(sp + src);
        }
        __syncthreads();

        // ---- S = Q*K^T (fp16x3, chain restart) ----
        float accm[8][4];
#pragma unroll
        for (int ks = 0; ks < 4; ++ks) {
            unsigned ah[4], al[4];
            ldsm4(ah, aQH + ks*32);
            ldsm4(al, aQL + ks*32);
#pragma unroll
            for (int p = 0; p < 4; ++p) {
                unsigned bh[4], bl[4];
                ldsm4(bh, bKH + p*(16*144) + ks*32);
                ldsm4(bl, bKL + p*(16*144) + ks*32);
#pragma unroll
                for (int h = 0; h < 2; ++h) {
                    float* ac = accm[p*2 + h];
                    if (ks == 0) mma_fp16_z(ac, ah, bl[h], bl[h+2]);    // ab
                    else         mma_fp16(ac, ah, bl[h], bl[h+2]);
                    mma_fp16(ac, al, bh[h], bh[h+2]);                    // ba
                    mma_fp16(ac, ah, bh[h], bh[h+2]);                    // aa
                }
            }
        }

        // ---- online softmax (fp32) ----
        float mx0 = -1e30f, mx1 = -1e30f;
#pragma unroll
        for (int nt = 0; nt < 8; ++nt) {
            mx0 = fmaxf(mx0, fmaxf(accm[nt][0], accm[nt][1]));
            mx1 = fmaxf(mx1, fmaxf(accm[nt][2], accm[nt][3]));
        }
        mx0 = fmaxf(mx0, __shfl_xor_sync(0xffffffffu, mx0, 1));
        mx0 = fmaxf(mx0, __shfl_xor_sync(0xffffffffu, mx0, 2));
        mx1 = fmaxf(mx1, __shfl_xor_sync(0xffffffffu, mx1, 1));
        mx1 = fmaxf(mx1, __shfl_xor_sync(0xffffffffu, mx1, 2));
        float mn0 = fmaxf(mi0, mx0), mn1 = fmaxf(mi1, mx1);
        float cr0 = __expf(mi0 - mn0), cr1 = __expf(mi1 - mn1);
        mi0 = mn0; mi1 = mn1;
        float rs0 = 0.f, rs1 = 0.f;
#pragma unroll
        for (int nt = 0; nt < 8; ++nt) {
            float p00 = __expf(accm[nt][0] - mn0);
            float p01 = __expf(accm[nt][1] - mn0);
            float p10 = __expf(accm[nt][2] - mn1);
            float p11 = __expf(accm[nt][3] - mn1);
            rs0 += p00 + p01; rs1 += p10 + p11;
            unsigned short h0,l0,h1,l1;
            int colh = nt*8 + c0;
            split2(p00,h0,l0); split2(p01,h1,l1);
            *(unsigned*)(smc + PH_B + (warp*16 + r0)*144 + colh*2) = (unsigned)h0 | ((unsigned)h1<<16);
            *(unsigned*)(smc + PL_B + (warp*16 + r0)*144 + colh*2) = (unsigned)l0 | ((unsigned)l1<<16);
            split2(p10,h0,l0); split2(p11,h1,l1);
            *(unsigned*)(smc + PH_B + (warp*16 + r0 + 8)*144 + colh*2) = (unsigned)h0 | ((unsigned)h1<<16);
            *(unsigned*)(smc + PL_B + (warp*16 + r0 + 8)*144 + colh*2) = (unsigned)l0 | ((unsigned)l1<<16);
        }
        rs0 += __shfl_xor_sync(0xffffffffu, rs0, 1);
        rs0 += __shfl_xor_sync(0xffffffffu, rs0, 2);
        rs1 += __shfl_xor_sync(0xffffffffu, rs1, 1);
        rs1 += __shfl_xor_sync(0xffffffffu, rs1, 2);
        li0 = li0*cr0 + rs0;
        li1 = li1*cr1 + rs1;
        __syncwarp();

        // ---- O_chunk = P*V (fp16x3; V via trans ldsm, pairs (r0,r1)/(r2,r3)) ----
#pragma unroll
        for (int ks = 0; ks < 4; ++ks) {
            unsigned ah[4], al[4];
            ldsm4(ah, aPH + ks*32);
            ldsm4(al, aPL + ks*32);
#pragma unroll
            for (int p = 0; p < 4; ++p) {
                unsigned bh[4], bl[4];
                unsigned vaddr = smb + VH_B + (unsigned)(((lane & 15) + ks*16)*144)
                               + ((lane >> 4) << 4) + p*32;
                ldsm4t(bh, vaddr);
                ldsm4t(bl, vaddr + (VL_B - VH_B));
#pragma unroll
                for (int h = 0; h < 2; ++h) {
                    float* ac = accm[p*2 + h];
                    if (ks == 0) mma_fp16_z(ac, ah, bl[2*h], bl[2*h+1]);  // ab
                    else         mma_fp16(ac, ah, bl[2*h], bl[2*h+1]);
                    mma_fp16(ac, al, bh[2*h], bh[2*h+1]);                  // ba
                    mma_fp16(ac, ah, bh[2*h], bh[2*h+1]);                  // aa
                }
            }
        }
        // O = O*corr + O_chunk (fp32 RN)
#pragma unroll
        for (int nt = 0; nt < 8; ++nt) {
            O[nt][0] = O[nt][0]*cr0 + accm[nt][0];
            O[nt][1] = O[nt][1]*cr0 + accm[nt][1];
            O[nt][2] = O[nt][2]*cr1 + accm[nt][2];
            O[nt][3] = O[nt][3]*cr1 + accm[nt][3];
        }
    }

    // epilogue: normalize + scatter fp32 to g_O4
    float inv0 = 1.f/li0, inv1 = 1.f/li1;
    const int ma = q0 + warp*16 + r0;
#pragma unroll
    for (int nt = 0; nt < 8; ++nt) {
        int col = nt*8 + c0;
        *(float2*)(g_O4 + baseH + (size_t)ma*strideE + col) =
            make_float2(O[nt][0]*inv0, O[nt][1]*inv0);
        *(float2*)(g_O4 + baseH + (size_t)(ma + 8)*strideE + col) =
            make_float2(O[nt][2]*inv1, O[nt][3]*inv1);
    }
}

// ---------------------------------------------------------------------------
// denom[b,c] = sum_n O4[b,n,c]; g_inv = 64/denom (fp16-range guard; 1/64 via s1)
// ---------------------------------------------------------------------------
__global__ void colsum_part_kernel()
{
    int chunk = blockIdx.x;
    int bc    = blockIdx.y;
    int b  = bc / 3;
    int c  = (bc % 3)*256 + threadIdx.x;
    const float* p = g_O4 + ((size_t)b*NN + chunk*256)*EE + c;
    float s = 0.f;
#pragma unroll 8
    for (int n = 0; n < 256; ++n) {
        s += *p;
        p += EE;
    }
    g_part[chunk*(BB*EE) + b*EE + c] = s;
}

__global__ void colsum_reduce_kernel()
{
    int i = blockIdx.x*256 + threadIdx.x;
    float s = 0.f;
#pragma unroll
    for (int ch = 0; ch < 32; ++ch) s += g_part[ch*(BB*EE) + i];
    g_inv[i] = 64.0f / s;
}

// ---------------------------------------------------------------------------
extern "C" void kernel_launch(void* const* d_in, const int* in_sizes, int n_in,
                              void* d_out, int out_size)
{
    const float* query = (const float*)d_in[0];
    const float* key   = (const float*)d_in[1];
    const float* value = (const float*)d_in[2];
    const float* Wq = (const float*)d_in[3];
    const float* bq = (const float*)d_in[4];
    const float* Wk = (const float*)d_in[5];
    const float* bk = (const float*)d_in[6];
    const float* Wv = (const float*)d_in[7];
    const float* bv = (const float*)d_in[8];
    const float* Wo = (const float*)d_in[9];
    const float* bo = (const float*)d_in[10];
    float* out = (float*)d_out;

    float *pO4, *pInv;
    unsigned short *pQh, *pQl, *pKh, *pKl, *pVh, *pVl;
    cudaGetSymbolAddress((void**)&pO4,  g_O4);
    cudaGetSymbolAddress((void**)&pInv, g_inv);
    cudaGetSymbolAddress((void**)&pQh, g_pQh); cudaGetSymbolAddress((void**)&pQl, g_pQl);
    cudaGetSymbolAddress((void**)&pKh, g_pKh); cudaGetSymbolAddress((void**)&pKl, g_pKl);
    cudaGetSymbolAddress((void**)&pVh, g_pVh); cudaGetSymbolAddress((void**)&pVl, g_pVl);

    cudaFuncSetAttribute(attn_kernel,
                         cudaFuncAttributeMaxDynamicSharedMemorySize,
                         ATTN_SMEM_BYTES);
    cudaFuncSetAttribute(gemm768_tc2_kernel,
                         cudaFuncAttributeMaxDynamicSharedMemorySize,
                         GEMM_SMEM_BYTES);

    dim3 gg(6, 128);

    // 1. zero scatter buffer
    zero_O4_kernel<<<12288, 256>>>();

    // 2. projections -> fp16 hi/lo planes directly (Q scaled by 1/8)
    splitW_kernel<<<576, 256>>>(Wq);
    splitA_kernel<<<12288, 256>>>(query, nullptr);
    gemm768_tc2_kernel<<<gg, 512, GEMM_SMEM_BYTES>>>(bq, 1.0f, 0.125f, nullptr, pQh, pQl);

    splitW_kernel<<<576, 256>>>(Wk);
    splitA_kernel<<<12288, 256>>>(key, nullptr);
    gemm768_tc2_kernel<<<gg, 512, GEMM_SMEM_BYTES>>>(bk, 1.0f, 1.0f, nullptr, pKh, pKl);

    splitW_kernel<<<576, 256>>>(Wv);
    splitA_kernel<<<12288, 256>>>(value, nullptr);
    gemm768_tc2_kernel<<<gg, 512, GEMM_SMEM_BYTES>>>(bv, 1.0f, 1.0f, nullptr, pVh, pVl);

    // 3. dilated attention on tensor cores (56 instances x 16 q-tiles)
    attn_kernel<<<dim3(16, 56), 256, ATTN_SMEM_BYTES>>>();

    // 4. sequence-sum normalization factors (64/denom)
    colsum_part_kernel<<<dim3(32, 6), 256>>>();
    colsum_reduce_kernel<<<6, 256>>>();

    // 5. output projection; 64/denom folded into A-split, 1/64 via s1
    splitW_kernel<<<576, 256>>>(Wo);
    splitA_kernel<<<12288, 256>>>(pO4, pInv);
    gemm768_tc2_kernel<<<gg, 512, GEMM_SMEM_BYTES>>>(bo, 1.0f/64.0f, 1.0f, out, nullptr, nullptr);
}

// round 15
// speedup vs baseline: 2.1713x; 1.1190x over previous
#include <cuda_runtime.h>
#include <cuda_fp16.h>
#include <math.h>
#include <stdint.h>

// Problem constants
#define BB 2
#define NN 8192
#define EE 768
#define HH 12
#define DD 64
#define MTOT (BB*NN)        // 16384

// Scratch (device globals: allocation-guard safe)
__device__ float g_O4[BB*NN*EE];
__device__ float g_part[32*BB*EE];
__device__ float g_inv[BB*EE];

#define ASZ (MTOT*EE)
#define WSZ (EE*EE)
// GEMM operand split planes
__device__ unsigned short g_sA[2*ASZ];
__device__ unsigned short g_sW[2*WSZ];
// Q/K/V fp16 hi/lo planes (written by projection GEMM epilogues)
__device__ unsigned short g_pQh[ASZ], g_pQl[ASZ];
__device__ unsigned short g_pKh[ASZ], g_pKl[ASZ];
__device__ unsigned short g_pVh[ASZ], g_pVl[ASZ];

// ---------------------------------------------------------------------------
__global__ void zero_O4_kernel() {
    size_t i = (size_t)blockIdx.x * blockDim.x + threadIdx.x;
    ((float4*)g_O4)[i] = make_float4(0.f, 0.f, 0.f, 0.f);
}

// ---------------------------------------------------------------------------
// fp16 2-way split: x ~ a + b
// ---------------------------------------------------------------------------
__device__ __forceinline__ void split2(float x, unsigned short &a, unsigned short &b) {
    __half ha = __float2half_rn(x);
    float r1 = x - __half2float(ha);
    __half hb = __float2half_rn(r1);
    a = __half_as_ushort(ha);
    b = __half_as_ushort(hb);
}

__global__ void splitA_kernel(const float* __restrict__ A,
                              const float* __restrict__ colscale) {
    int i = blockIdx.x*256 + threadIdx.x;
    float4 av = ((const float4*)A)[i];
    if (colscale) {
        int kq = i % 192;
        int m  = i / 192;
        float4 cs = ((const float4*)colscale)[(m >> 13)*192 + kq];
        av.x *= cs.x; av.y *= cs.y; av.z *= cs.z; av.w *= cs.w;
    }
    ushort4 sa, sb;
    split2(av.x, sa.x, sb.x); split2(av.y, sa.y, sb.y);
    split2(av.z, sa.z, sb.z); split2(av.w, sa.w, sb.w);
    ((ushort4*)g_sA)[i]         = sa;
    ((ushort4*)(g_sA + ASZ))[i] = sb;
}

__global__ void splitW_kernel(const float* __restrict__ W) {
    int i = blockIdx.x*256 + threadIdx.x;
    float4 wv = ((const float4*)W)[i];
    ushort4 sa, sb;
    split2(wv.x, sa.x, sb.x); split2(wv.y, sa.y, sb.y);
    split2(wv.z, sa.z, sb.z); split2(wv.w, sa.w, sb.w);
    ((ushort4*)g_sW)[i]         = sa;
    ((ushort4*)(g_sW + WSZ))[i] = sb;
}

// ---------------------------------------------------------------------------
// MMA helpers
// ---------------------------------------------------------------------------
__device__ __forceinline__ void mma_fp16(float* acc, const unsigned* a, unsigned b0, unsigned b1) {
    asm volatile(
        "mma.sync.aligned.m16n8k16.row.col.f32.f16.f16.f32 "
        "{%0,%1,%2,%3}, {%4,%5,%6,%7}, {%8,%9}, {%0,%1,%2,%3};"
        : "+f"(acc[0]), "+f"(acc[1]), "+f"(acc[2]), "+f"(acc[3])
        : "r"(a[0]), "r"(a[1]), "r"(a[2]), "r"(a[3]), "r"(b0), "r"(b1));
}
__device__ __forceinline__ void mma_fp16_z(float* d, const unsigned* a, unsigned b0, unsigned b1) {
    asm volatile(
        "mma.sync.aligned.m16n8k16.row.col.f32.f16.f16.f32 "
        "{%0,%1,%2,%3}, {%4,%5,%6,%7}, {%8,%9}, {%10,%11,%12,%13};"
        : "=f"(d[0]), "=f"(d[1]), "=f"(d[2]), "=f"(d[3])
        : "r"(a[0]), "r"(a[1]), "r"(a[2]), "r"(a[3]), "r"(b0), "r"(b1),
          "f"(0.f), "f"(0.f), "f"(0.f), "f"(0.f));
}
__device__ __forceinline__ void ldsm4(unsigned* d, unsigned addr) {
    asm volatile("ldmatrix.sync.aligned.m8n8.x4.shared.b16 {%0,%1,%2,%3}, [%4];"
                 : "=r"(d[0]), "=r"(d[1]), "=r"(d[2]), "=r"(d[3]) : "r"(addr));
}
__device__ __forceinline__ void ldsm4t(unsigned* d, unsigned addr) {
    asm volatile("ldmatrix.sync.aligned.m8n8.x4.trans.shared.b16 {%0,%1,%2,%3}, [%4];"
                 : "=r"(d[0]), "=r"(d[1]), "=r"(d[2]), "=r"(d[3]) : "r"(addr));
}
__device__ __forceinline__ void cp_async16(unsigned saddr, const void* g) {
    asm volatile("cp.async.ca.shared.global [%0], [%1], 16;"
                 :: "r"(saddr), "l"(g) : "memory");
}

// ---------------------------------------------------------------------------
// fp16x3 projection GEMM with 4-stage cp.async pipeline.
// CTA 128x128, K-block 32, 16 warps (4Mx4N), warp tile 32x32.
// Epilogue writes EITHER fp32 C OR fp16 hi/lo planes of (acc*s1 + bias)*s2.
// ---------------------------------------------------------------------------
#define BLDA 40
#define SPL  (128*BLDA)
#define SPLB (SPL*2u)
#define STG  (4*SPL)
#define STGB (4*SPLB)              // 40960 bytes per stage
#define NSTAGE 4
#define GEMM_SMEM_BYTES (NSTAGE*STGB)   // 163840

__global__ __launch_bounds__(512) void gemm768_tc2_kernel(
    const float* __restrict__ bias, float s1, float s2, float* __restrict__ C,
    unsigned short* __restrict__ outH, unsigned short* __restrict__ outL)
{
    extern __shared__ unsigned short smu[];

    const int tid  = threadIdx.x;
    const int lane = tid & 31;
    const int wid  = tid >> 5;
    const int warp_m = wid & 3;
    const int warp_n = wid >> 2;
    const int m0 = blockIdx.y * 128;
    const int n0 = blockIdx.x * 128;

    const int lrow = tid >> 2;     // 0..127
    const int lcol = tid & 3;      // 16B chunk along 32-wide k

    float acc[2][4][4];
    float accm[2][4][4];
#pragma unroll
    for (int mt = 0; mt < 2; ++mt)
#pragma unroll
        for (int nt = 0; nt < 4; ++nt)
#pragma unroll
            for (int r = 0; r < 4; ++r) acc[mt][nt][r] = 0.f;

    const unsigned smbase = (unsigned)__cvta_generic_to_shared(smu);
    const unsigned a_off = (unsigned)((warp_m*32 + (lane & 15))*80) + ((lane >> 4) << 4);
    const unsigned b_off = (unsigned)((warp_n*32 + (lane & 15))*80) + ((lane >> 4) << 4);

    const int SA[3] = {0, 1, 0};
    const int SB[3] = {1, 0, 0};

    // issue cp.asyncs for K-block t into stage buffer; always commit a group
#define ISSUE_STAGE(t)                                                              \
    {                                                                               \
        if ((t) < 24) {                                                             \
            const int kb_ = (t)*32;                                                 \
            const unsigned dst_ = smbase + (unsigned)((t) % NSTAGE)*STGB            \
                                + (unsigned)(lrow*80 + lcol*16);                    \
            _Pragma("unroll")                                                       \
            for (int pl = 0; pl < 2; ++pl) {                                        \
                cp_async16(dst_ + pl*SPLB,                                          \
                    g_sA + (size_t)pl*ASZ + (size_t)(m0 + lrow)*768 + kb_ + lcol*8);\
                cp_async16(dst_ + (2+pl)*SPLB,                                      \
                    g_sW + (size_t)pl*WSZ + (size_t)(n0 + lrow)*768 + kb_ + lcol*8);\
            }                                                                       \
        }                                                                           \
        asm volatile("cp.async.commit_group;" ::: "memory");                        \
    }

    ISSUE_STAGE(0); ISSUE_STAGE(1); ISSUE_STAGE(2);

    for (int t = 0; t < 24; ++t) {
        asm volatile("cp.async.wait_group 2;" ::: "memory");
        __syncthreads();
        ISSUE_STAGE(t + 3);

        const unsigned stg = smbase + (unsigned)(t % NSTAGE)*STGB;
#pragma unroll
        for (int ks = 0; ks < 2; ++ks) {
            unsigned af[2][2][4];
#pragma unroll
            for (int mt = 0; mt < 2; ++mt)
#pragma unroll
                for (int s = 0; s < 2; ++s)
                    ldsm4(af[mt][s], stg + s*SPLB + a_off + mt*(16*80) + ks*32);

#pragma unroll
            for (int p = 0; p < 2; ++p) {
                unsigned bf[2][4];
#pragma unroll
                for (int s = 0; s < 2; ++s)
                    ldsm4(bf[s], stg + (2+s)*SPLB + b_off + p*(16*80) + ks*32);
#pragma unroll
                for (int prod = 0; prod < 3; ++prod) {
                    const int sa = SA[prod], sb = SB[prod];
#pragma unroll
                    for (int mt = 0; mt < 2; ++mt)
#pragma unroll
                        for (int h = 0; h < 2; ++h) {
                            float* ac = accm[mt][p*2 + h];
                            if (ks == 0 && prod == 0)
                                mma_fp16_z(ac, af[mt][sa], bf[sb][h], bf[sb][h+2]);
                            else
                                mma_fp16(ac, af[mt][sa], bf[sb][h], bf[sb][h+2]);
                        }
                }
            }
        }
#pragma unroll
        for (int mt = 0; mt < 2; ++mt)
#pragma unroll
            for (int nt = 0; nt < 4; ++nt)
#pragma unroll
                for (int r = 0; r < 4; ++r)
                    acc[mt][nt][r] += accm[mt][nt][r];
        __syncthreads();
    }
#undef ISSUE_STAGE

    const int r0 = lane >> 2;
    const int c0 = (lane & 3) * 2;
#pragma unroll
    for (int mt = 0; mt < 2; ++mt) {
#pragma unroll
        for (int nt = 0; nt < 4; ++nt) {
            int col = n0 + warp_n*32 + nt*8 + c0;
            float b0 = bias[col], b1 = bias[col + 1];
            int row_t = m0 + warp_m*32 + mt*16 + r0;
            float v00 = (acc[mt][nt][0]*s1 + b0)*s2, v01 = (acc[mt][nt][1]*s1 + b1)*s2;
            float v10 = (acc[mt][nt][2]*s1 + b0)*s2, v11 = (acc[mt][nt][3]*s1 + b1)*s2;
            if (outH) {
                unsigned short h0,l0,h1,l1;
                split2(v00,h0,l0); split2(v01,h1,l1);
                *(unsigned*)(outH + (size_t)row_t*768 + col) = (unsigned)h0 | ((unsigned)h1<<16);
                *(unsigned*)(outL + (size_t)row_t*768 + col) = (unsigned)l0 | ((unsigned)l1<<16);
                split2(v10,h0,l0); split2(v11,h1,l1);
                *(unsigned*)(outH + (size_t)(row_t+8)*768 + col) = (unsigned)h0 | ((unsigned)h1<<16);
                *(unsigned*)(outL + (size_t)(row_t+8)*768 + col) = (unsigned)l0 | ((unsigned)l1<<16);
            } else {
                *(float2*)(C + (size_t)row_t*768 + col)       = make_float2(v00, v01);
                *(float2*)(C + (size_t)(row_t + 8)*768 + col) = make_float2(v10, v11);
            }
        }
    }
}

// ---------------------------------------------------------------------------
// fp16x3 MMA dilated flash attention (validated R14 — unchanged).
// ---------------------------------------------------------------------------
#define QH_B 0u
#define QL_B 18432u
#define KH_B 36864u
#define KL_B 46080u
#define VH_B 55296u
#define VL_B 64512u
#define PH_B 73728u
#define PL_B 92160u
#define ATTN_SMEM_BYTES 110592

__global__ __launch_bounds__(256) void attn_kernel()
{
    extern __shared__ unsigned short smh[];
    const int tid  = threadIdx.x;
    const int lane = tid & 31;
    const int warp = tid >> 5;

    const int inst = blockIdx.y;
    int grp, b, seg, hl;
    if (inst < 32)      { grp = 0; b = inst >> 4;        seg = (inst >> 2) & 3; hl = inst & 3; }
    else if (inst < 48) { int r = inst - 32; grp = 1; b = r >> 3; seg = (r >> 2) & 1; hl = r & 3; }
    else                { int r = inst - 48; grp = 2; b = r >> 2; seg = 0;            hl = r & 3; }
    const int rate = 1 << grp;
    const int slen = 2048 << grp;
    const int off  = grp;
    const int head = grp*4 + hl;
    const int q0   = blockIdx.x * 128;

    const size_t baseH = (size_t)b*NN*EE + (size_t)(seg*slen + off)*EE + head*DD;
    const int strideE = rate * EE;

    const unsigned smb = (unsigned)__cvta_generic_to_shared(smh);
    char* smc = (char*)smh;

#pragma unroll
    for (int i = 0; i < 4; ++i) {
        int idx = tid + i*256;
        int row = idx >> 3, c = idx & 7;
        size_t src = baseH + (size_t)(q0 + row)*strideE + c*8;
        *(uint4*)(smc + QH_B + row*144 + c*16) = *(const uint4*)(g_pQh + src);
        *(uint4*)(smc + QL_B + row*144 + c*16) = *(const uint4*)(g_pQl + src);
    }

    const unsigned aQH = smb + QH_B + (unsigned)((warp*16 + (lane & 15))*144) + ((lane >> 4) << 4);
    const unsigned aQL = aQH + (QL_B - QH_B);
    const unsigned bKH = smb + KH_B + (unsigned)((lane & 15)*144) + ((lane >> 4) << 4);
    const unsigned bKL = bKH + (KL_B - KH_B);
    const unsigned aPH = smb + PH_B + (unsigned)((warp*16 + (lane & 15))*144) + ((lane >> 4) << 4);
    const unsigned aPL = aPH + (PL_B - PH_B);

    float O[8][4];
#pragma unroll
    for (int nt = 0; nt < 8; ++nt)
#pragma unroll
        for (int r = 0; r < 4; ++r) O[nt][r] = 0.f;
    float mi0 = -1e30f, mi1 = -1e30f, li0 = 0.f, li1 = 0.f;

    const int r0 = lane >> 2;
    const int c0 = (lane & 3)*2;

    for (int kt = 0; kt < 32; ++kt) {
        const int k0 = kt*64;
        __syncthreads();
#pragma unroll
        for (int i = 0; i < 8; ++i) {
            int idx = tid + i*256;
            int arr = idx >> 9;
            int rem = idx & 511;
            int row = rem >> 3, c = rem & 7;
            size_t src = baseH + (size_t)(k0 + row)*strideE + c*8;
            const unsigned short* sp = (arr == 0) ? g_pKh : (arr == 1) ? g_pKl
                                     : (arr == 2) ? g_pVh : g_pVl;
            unsigned dst = (arr == 0) ? KH_B : (arr == 1) ? KL_B
                         : (arr == 2) ? VH_B : VL_B;
            *(uint4*)(smc + dst + row*144 + c*16) = *(const uint4*)(sp + src);
        }
        __syncthreads();

        float accm[8][4];
#pragma unroll
        for (int ks = 0; ks < 4; ++ks) {
            unsigned ah[4], al[4];
            ldsm4(ah, aQH + ks*32);
            ldsm4(al, aQL + ks*32);
#pragma unroll
            for (int p = 0; p < 4; ++p) {
                unsigned bh[4], bl[4];
                ldsm4(bh, bKH + p*(16*144) + ks*32);
                ldsm4(bl, bKL + p*(16*144) + ks*32);
#pragma unroll
                for (int h = 0; h < 2; ++h) {
                    float* ac = accm[p*2 + h];
                    if (ks == 0) mma_fp16_z(ac, ah, bl[h], bl[h+2]);
                    else         mma_fp16(ac, ah, bl[h], bl[h+2]);
                    mma_fp16(ac, al, bh[h], bh[h+2]);
                    mma_fp16(ac, ah, bh[h], bh[h+2]);
                }
            }
        }

        float mx0 = -1e30f, mx1 = -1e30f;
#pragma unroll
        for (int nt = 0; nt < 8; ++nt) {
            mx0 = fmaxf(mx0, fmaxf(accm[nt][0], accm[nt][1]));
            mx1 = fmaxf(mx1, fmaxf(accm[nt][2], accm[nt][3]));
        }
        mx0 = fmaxf(mx0, __shfl_xor_sync(0xffffffffu, mx0, 1));
        mx0 = fmaxf(mx0, __shfl_xor_sync(0xffffffffu, mx0, 2));
        mx1 = fmaxf(mx1, __shfl_xor_sync(0xffffffffu, mx1, 1));
        mx1 = fmaxf(mx1, __shfl_xor_sync(0xffffffffu, mx1, 2));
        float mn0 = fmaxf(mi0, mx0), mn1 = fmaxf(mi1, mx1);
        float cr0 = __expf(mi0 - mn0), cr1 = __expf(mi1 - mn1);
        mi0 = mn0; mi1 = mn1;
        float rs0 = 0.f, rs1 = 0.f;
#pragma unroll
        for (int nt = 0; nt < 8; ++nt) {
            float p00 = __expf(accm[nt][0] - mn0);
            float p01 = __expf(accm[nt][1] - mn0);
            float p10 = __expf(accm[nt][2] - mn1);
            float p11 = __expf(accm[nt][3] - mn1);
            rs0 += p00 + p01; rs1 += p10 + p11;
            unsigned short h0,l0,h1,l1;
            int colh = nt*8 + c0;
            split2(p00,h0,l0); split2(p01,h1,l1);
            *(unsigned*)(smc + PH_B + (warp*16 + r0)*144 + colh*2) = (unsigned)h0 | ((unsigned)h1<<16);
            *(unsigned*)(smc + PL_B + (warp*16 + r0)*144 + colh*2) = (unsigned)l0 | ((unsigned)l1<<16);
            split2(p10,h0,l0); split2(p11,h1,l1);
            *(unsigned*)(smc + PH_B + (warp*16 + r0 + 8)*144 + colh*2) = (unsigned)h0 | ((unsigned)h1<<16);
            *(unsigned*)(smc + PL_B + (warp*16 + r0 + 8)*144 + colh*2) = (unsigned)l0 | ((unsigned)l1<<16);
        }
        rs0 += __shfl_xor_sync(0xffffffffu, rs0, 1);
        rs0 += __shfl_xor_sync(0xffffffffu, rs0, 2);
        rs1 += __shfl_xor_sync(0xffffffffu, rs1, 1);
        rs1 += __shfl_xor_sync(0xffffffffu, rs1, 2);
        li0 = li0*cr0 + rs0;
        li1 = li1*cr1 + rs1;
        __syncwarp();

#pragma unroll
        for (int ks = 0; ks < 4; ++ks) {
            unsigned ah[4], al[4];
            ldsm4(ah, aPH + ks*32);
            ldsm4(al, aPL + ks*32);
#pragma unroll
            for (int p = 0; p < 4; ++p) {
                unsigned bh[4], bl[4];
                unsigned vaddr = smb + VH_B + (unsigned)(((lane & 15) + ks*16)*144)
                               + ((lane >> 4) << 4) + p*32;
                ldsm4t(bh, vaddr);
                ldsm4t(bl, vaddr + (VL_B - VH_B));
#pragma unroll
                for (int h = 0; h < 2; ++h) {
                    float* ac = accm[p*2 + h];
                    if (ks == 0) mma_fp16_z(ac, ah, bl[2*h], bl[2*h+1]);
                    else         mma_fp16(ac, ah, bl[2*h], bl[2*h+1]);
                    mma_fp16(ac, al, bh[2*h], bh[2*h+1]);
                    mma_fp16(ac, ah, bh[2*h], bh[2*h+1]);
                }
            }
        }
#pragma unroll
        for (int nt = 0; nt < 8; ++nt) {
            O[nt][0] = O[nt][0]*cr0 + accm[nt][0];
            O[nt][1] = O[nt][1]*cr0 + accm[nt][1];
            O[nt][2] = O[nt][2]*cr1 + accm[nt][2];
            O[nt][3] = O[nt][3]*cr1 + accm[nt][3];
        }
    }

    float inv0 = 1.f/li0, inv1 = 1.f/li1;
    const int ma = q0 + warp*16 + r0;
#pragma unroll
    for (int nt = 0; nt < 8; ++nt) {
        int col = nt*8 + c0;
        *(float2*)(g_O4 + baseH + (size_t)ma*strideE + col) =
            make_float2(O[nt][0]*inv0, O[nt][1]*inv0);
        *(float2*)(g_O4 + baseH + (size_t)(ma + 8)*strideE + col) =
            make_float2(O[nt][2]*inv1, O[nt][3]*inv1);
    }
}

// ---------------------------------------------------------------------------
// denom[b,c] = sum_n O4[b,n,c]; g_inv = 64/denom (fp16-range guard; 1/64 via s1)
// ---------------------------------------------------------------------------
__global__ void colsum_part_kernel()
{
    int chunk = blockIdx.x;
    int bc    = blockIdx.y;
    int b  = bc / 3;
    int c  = (bc % 3)*256 + threadIdx.x;
    const float* p = g_O4 + ((size_t)b*NN + chunk*256)*EE + c;
    float s = 0.f;
#pragma unroll 8
    for (int n = 0; n < 256; ++n) {
        s += *p;
        p += EE;
    }
    g_part[chunk*(BB*EE) + b*EE + c] = s;
}

__global__ void colsum_reduce_kernel()
{
    int i = blockIdx.x*256 + threadIdx.x;
    float s = 0.f;
#pragma unroll
    for (int ch = 0; ch < 32; ++ch) s += g_part[ch*(BB*EE) + i];
    g_inv[i] = 64.0f / s;
}

// ---------------------------------------------------------------------------
extern "C" void kernel_launch(void* const* d_in, const int* in_sizes, int n_in,
                              void* d_out, int out_size)
{
    const float* query = (const float*)d_in[0];
    const float* key   = (const float*)d_in[1];
    const float* value = (const float*)d_in[2];
    const float* Wq = (const float*)d_in[3];
    const float* bq = (const float*)d_in[4];
    const float* Wk = (const float*)d_in[5];
    const float* bk = (const float*)d_in[6];
    const float* Wv = (const float*)d_in[7];
    const float* bv = (const float*)d_in[8];
    const float* Wo = (const float*)d_in[9];
    const float* bo = (const float*)d_in[10];
    float* out = (float*)d_out;

    float *pO4, *pInv;
    unsigned short *pQh, *pQl, *pKh, *pKl, *pVh, *pVl;
    cudaGetSymbolAddress((void**)&pO4,  g_O4);
    cudaGetSymbolAddress((void**)&pInv, g_inv);
    cudaGetSymbolAddress((void**)&pQh, g_pQh); cudaGetSymbolAddress((void**)&pQl, g_pQl);
    cudaGetSymbolAddress((void**)&pKh, g_pKh); cudaGetSymbolAddress((void**)&pKl, g_pKl);
    cudaGetSymbolAddress((void**)&pVh, g_pVh); cudaGetSymbolAddress((void**)&pVl, g_pVl);

    cudaFuncSetAttribute(attn_kernel,
                         cudaFuncAttributeMaxDynamicSharedMemorySize,
                         ATTN_SMEM_BYTES);
    cudaFuncSetAttribute(gemm768_tc2_kernel,
                         cudaFuncAttributeMaxDynamicSharedMemorySize,
                         GEMM_SMEM_BYTES);

    dim3 gg(6, 128);

    // 1. zero scatter buffer
    zero_O4_kernel<<<12288, 256>>>();

    // 2. projections -> fp16 hi/lo planes directly (Q scaled by 1/8)
    splitW_kernel<<<576, 256>>>(Wq);
    splitA_kernel<<<12288, 256>>>(query, nullptr);
    gemm768_tc2_kernel<<<gg, 512, GEMM_SMEM_BYTES>>>(bq, 1.0f, 0.125f, nullptr, pQh, pQl);

    splitW_kernel<<<576, 256>>>(Wk);
    splitA_kernel<<<12288, 256>>>(key, nullptr);
    gemm768_tc2_kernel<<<gg, 512, GEMM_SMEM_BYTES>>>(bk, 1.0f, 1.0f, nullptr, pKh, pKl);

    splitW_kernel<<<576, 256>>>(Wv);
    splitA_kernel<<<12288, 256>>>(value, nullptr);
    gemm768_tc2_kernel<<<gg, 512, GEMM_SMEM_BYTES>>>(bv, 1.0f, 1.0f, nullptr, pVh, pVl);

    // 3. dilated attention on tensor cores (56 instances x 16 q-tiles)
    attn_kernel<<<dim3(16, 56), 256, ATTN_SMEM_BYTES>>>();

    // 4. sequence-sum normalization factors (64/denom)
    colsum_part_kernel<<<dim3(32, 6), 256>>>();
    colsum_reduce_kernel<<<6, 256>>>();

    // 5. output projection; 64/denom folded into A-split, 1/64 via s1
    splitW_kernel<<<576, 256>>>(Wo);
    splitA_kernel<<<12288, 256>>>(pO4, pInv);
    gemm768_tc2_kernel<<<gg, 512, GEMM_SMEM_BYTES>>>(bo, 1.0f/64.0f, 1.0f, out, nullptr, nullptr);
}

// round 16
// speedup vs baseline: 2.2999x; 1.0592x over previous
#include <cuda_runtime.h>
#include <cuda_fp16.h>
#include <math.h>
#include <stdint.h>

// Problem constants
#define BB 2
#define NN 8192
#define EE 768
#define HH 12
#define DD 64
#define MTOT (BB*NN)        // 16384

// Scratch (device globals: allocation-guard safe)
__device__ float g_O4[BB*NN*EE];
__device__ float g_part[32*BB*EE];
__device__ float g_inv[BB*EE];

#define ASZ (MTOT*EE)
#define WSZ (EE*EE)
// 3-slot split planes: slot z holds [plane0, plane1] contiguously
__device__ unsigned short g_sA3[3*2*ASZ];
__device__ unsigned short g_sW3[3*2*WSZ];
// Q/K/V fp16 hi/lo planes (written by projection GEMM epilogues)
__device__ unsigned short g_pQh[ASZ], g_pQl[ASZ];
__device__ unsigned short g_pKh[ASZ], g_pKl[ASZ];
__device__ unsigned short g_pVh[ASZ], g_pVl[ASZ];

// ---------------------------------------------------------------------------
__global__ void zero_O4_kernel() {
    size_t i = (size_t)blockIdx.x * blockDim.x + threadIdx.x;
    ((float4*)g_O4)[i] = make_float4(0.f, 0.f, 0.f, 0.f);
}

// ---------------------------------------------------------------------------
// fp16 2-way split: x ~ a + b
// ---------------------------------------------------------------------------
__device__ __forceinline__ void split2(float x, unsigned short &a, unsigned short &b) {
    __half ha = __float2half_rn(x);
    float r1 = x - __half2float(ha);
    __half hb = __float2half_rn(r1);
    a = __half_as_ushort(ha);
    b = __half_as_ushort(hb);
}

// merged A-split for the three projection inputs (blockIdx.y selects tensor)
__global__ void splitA3_kernel(const float* __restrict__ q,
                               const float* __restrict__ k,
                               const float* __restrict__ v) {
    int i = blockIdx.x*256 + threadIdx.x;
    const float* A = (blockIdx.y == 0) ? q : (blockIdx.y == 1) ? k : v;
    unsigned short* dst = g_sA3 + (size_t)blockIdx.y*2*ASZ;
    float4 av = ((const float4*)A)[i];
    ushort4 sa, sb;
    split2(av.x, sa.x, sb.x); split2(av.y, sa.y, sb.y);
    split2(av.z, sa.z, sb.z); split2(av.w, sa.w, sb.w);
    ((ushort4*)dst)[i]         = sa;
    ((ushort4*)(dst + ASZ))[i] = sb;
}

// A-split of g_O4 with per-(b,col) colscale g_inv (writes slot 0)
__global__ void splitA_cs_kernel() {
    int i = blockIdx.x*256 + threadIdx.x;
    float4 av = ((const float4*)g_O4)[i];
    int kq = i % 192;
    int m  = i / 192;
    float4 cs = ((const float4*)g_inv)[(m >> 13)*192 + kq];
    av.x *= cs.x; av.y *= cs.y; av.z *= cs.z; av.w *= cs.w;
    ushort4 sa, sb;
    split2(av.x, sa.x, sb.x); split2(av.y, sa.y, sb.y);
    split2(av.z, sa.z, sb.z); split2(av.w, sa.w, sb.w);
    ((ushort4*)g_sA3)[i]         = sa;
    ((ushort4*)(g_sA3 + ASZ))[i] = sb;
}

__global__ void splitW3_kernel(const float* __restrict__ wq,
                               const float* __restrict__ wk,
                               const float* __restrict__ wv) {
    int i = blockIdx.x*256 + threadIdx.x;
    const float* W = (blockIdx.y == 0) ? wq : (blockIdx.y == 1) ? wk : wv;
    unsigned short* dst = g_sW3 + (size_t)blockIdx.y*2*WSZ;
    float4 wvv = ((const float4*)W)[i];
    ushort4 sa, sb;
    split2(wvv.x, sa.x, sb.x); split2(wvv.y, sa.y, sb.y);
    split2(wvv.z, sa.z, sb.z); split2(wvv.w, sa.w, sb.w);
    ((ushort4*)dst)[i]         = sa;
    ((ushort4*)(dst + WSZ))[i] = sb;
}

__global__ void splitW1_kernel(const float* __restrict__ W) {
    int i = blockIdx.x*256 + threadIdx.x;
    float4 wvv = ((const float4*)W)[i];
    ushort4 sa, sb;
    split2(wvv.x, sa.x, sb.x); split2(wvv.y, sa.y, sb.y);
    split2(wvv.z, sa.z, sb.z); split2(wvv.w, sa.w, sb.w);
    ((ushort4*)g_sW3)[i]         = sa;
    ((ushort4*)(g_sW3 + WSZ))[i] = sb;
}

// ---------------------------------------------------------------------------
// MMA helpers
// ---------------------------------------------------------------------------
__device__ __forceinline__ void mma_fp16(float* acc, const unsigned* a, unsigned b0, unsigned b1) {
    asm volatile(
        "mma.sync.aligned.m16n8k16.row.col.f32.f16.f16.f32 "
        "{%0,%1,%2,%3}, {%4,%5,%6,%7}, {%8,%9}, {%0,%1,%2,%3};"
        : "+f"(acc[0]), "+f"(acc[1]), "+f"(acc[2]), "+f"(acc[3])
        : "r"(a[0]), "r"(a[1]), "r"(a[2]), "r"(a[3]), "r"(b0), "r"(b1));
}
__device__ __forceinline__ void mma_fp16_z(float* d, const unsigned* a, unsigned b0, unsigned b1) {
    asm volatile(
        "mma.sync.aligned.m16n8k16.row.col.f32.f16.f16.f32 "
        "{%0,%1,%2,%3}, {%4,%5,%6,%7}, {%8,%9}, {%10,%11,%12,%13};"
        : "=f"(d[0]), "=f"(d[1]), "=f"(d[2]), "=f"(d[3])
        : "r"(a[0]), "r"(a[1]), "r"(a[2]), "r"(a[3]), "r"(b0), "r"(b1),
          "f"(0.f), "f"(0.f), "f"(0.f), "f"(0.f));
}
__device__ __forceinline__ void ldsm4(unsigned* d, unsigned addr) {
    asm volatile("ldmatrix.sync.aligned.m8n8.x4.shared.b16 {%0,%1,%2,%3}, [%4];"
                 : "=r"(d[0]), "=r"(d[1]), "=r"(d[2]), "=r"(d[3]) : "r"(addr));
}
__device__ __forceinline__ void ldsm4t(unsigned* d, unsigned addr) {
    asm volatile("ldmatrix.sync.aligned.m8n8.x4.trans.shared.b16 {%0,%1,%2,%3}, [%4];"
                 : "=r"(d[0]), "=r"(d[1]), "=r"(d[2]), "=r"(d[3]) : "r"(addr));
}
__device__ __forceinline__ void cp_async16(unsigned saddr, const void* g) {
    asm volatile("cp.async.ca.shared.global [%0], [%1], 16;"
                 :: "r"(saddr), "l"(g) : "memory");
}

// ---------------------------------------------------------------------------
// fp16x3 GEMM core: 4-stage cp.async pipeline + fragment software pipeline.
// CTA 128x128, K-block 32, 16 warps (4Mx4N), warp tile 32x32.
// Per-accumulator product order (ab,ba,aa per ks) identical to R13-R15.
// ---------------------------------------------------------------------------
#define BLDA 40
#define SPL  (128*BLDA)
#define SPLB (SPL*2u)
#define STGB (4*SPLB)              // 40960 bytes per stage
#define NSTAGE 4
#define GEMM_SMEM_BYTES (NSTAGE*STGB)   // 163840

__device__ __forceinline__ void gemm_core(
    const unsigned short* __restrict__ sA,   // [2 planes x ASZ]
    const unsigned short* __restrict__ sW,   // [2 planes x WSZ]
    const float* __restrict__ bias, float s1, float s2,
    float* __restrict__ C, unsigned short* __restrict__ outH,
    unsigned short* __restrict__ outL)
{
    extern __shared__ unsigned short smu[];
    const int tid  = threadIdx.x;
    const int lane = tid & 31;
    const int wid  = tid >> 5;
    const int warp_m = wid & 3;
    const int warp_n = wid >> 2;
    const int m0 = blockIdx.y * 128;
    const int n0 = blockIdx.x * 128;
    const int lrow = tid >> 2;
    const int lcol = tid & 3;

    float acc[2][4][4];
    float accm[2][4][4];
#pragma unroll
    for (int mt = 0; mt < 2; ++mt)
#pragma unroll
        for (int nt = 0; nt < 4; ++nt)
#pragma unroll
            for (int r = 0; r < 4; ++r) acc[mt][nt][r] = 0.f;

    const unsigned smbase = (unsigned)__cvta_generic_to_shared(smu);
    const unsigned a_off = (unsigned)((warp_m*32 + (lane & 15))*80) + ((lane >> 4) << 4);
    const unsigned b_off = (unsigned)((warp_n*32 + (lane & 15))*80) + ((lane >> 4) << 4);
    const unsigned dst_off = (unsigned)(lrow*80 + lcol*16);

    // strength-reduced loader bases
    const unsigned short* pA = sA + (size_t)(m0 + lrow)*768 + lcol*8;
    const unsigned short* pW = sW + (size_t)(n0 + lrow)*768 + lcol*8;

#define ISSUE_STAGE(t)                                                          \
    {                                                                           \
        if ((t) < 24) {                                                         \
            const unsigned dst_ = smbase + (unsigned)((t) % NSTAGE)*STGB + dst_off; \
            const unsigned short* a_ = pA + (t)*32;                             \
            const unsigned short* w_ = pW + (t)*32;                             \
            cp_async16(dst_,          a_);                                      \
            cp_async16(dst_ + SPLB,   a_ + ASZ);                                \
            cp_async16(dst_ + 2*SPLB, w_);                                      \
            cp_async16(dst_ + 3*SPLB, w_ + WSZ);                                \
        }                                                                       \
        asm volatile("cp.async.commit_group;" ::: "memory");                    \
    }

    ISSUE_STAGE(0); ISSUE_STAGE(1); ISSUE_STAGE(2);

    const int SA[3] = {0, 1, 0};
    const int SB[3] = {1, 0, 0};

    for (int t = 0; t < 24; ++t) {
        asm volatile("cp.async.wait_group 2;" ::: "memory");
        __syncthreads();
        ISSUE_STAGE(t + 3);

        const unsigned stg = smbase + (unsigned)(t % NSTAGE)*STGB;

        // fragment pipeline: af[ks][mt][s], bf[buf][s]
        unsigned af[2][2][2][4];
        unsigned bf[2][2][4];
#pragma unroll
        for (int mt = 0; mt < 2; ++mt)
#pragma unroll
            for (int s = 0; s < 2; ++s)
                ldsm4(af[0][mt][s], stg + s*SPLB + a_off + mt*(16*80));
#pragma unroll
        for (int s = 0; s < 2; ++s)
            ldsm4(bf[0][s], stg + (2+s)*SPLB + b_off);

#pragma unroll
        for (int u = 0; u < 4; ++u) {
            const int ks = u >> 1, p = u & 1, buf = u & 1;
            if (u < 3) {
                const int nks = (u+1) >> 1, np = (u+1) & 1;
#pragma unroll
                for (int s = 0; s < 2; ++s)
                    ldsm4(bf[buf^1][s], stg + (2+s)*SPLB + b_off + np*(16*80) + nks*32);
                if (u == 1) {
#pragma unroll
                    for (int mt = 0; mt < 2; ++mt)
#pragma unroll
                        for (int s = 0; s < 2; ++s)
                            ldsm4(af[1][mt][s], stg + s*SPLB + a_off + mt*(16*80) + 32);
                }
            }
#pragma unroll
            for (int prod = 0; prod < 3; ++prod) {
                const int sa = SA[prod], sb = SB[prod];
#pragma unroll
                for (int mt = 0; mt < 2; ++mt)
#pragma unroll
                    for (int h = 0; h < 2; ++h) {
                        float* ac = accm[mt][p*2 + h];
                        if (ks == 0 && prod == 0)
                            mma_fp16_z(ac, af[ks][mt][sa], bf[buf][sb][h], bf[buf][sb][h+2]);
                        else
                            mma_fp16(ac, af[ks][mt][sa], bf[buf][sb][h], bf[buf][sb][h+2]);
                    }
            }
        }
#pragma unroll
        for (int mt = 0; mt < 2; ++mt)
#pragma unroll
            for (int nt = 0; nt < 4; ++nt)
#pragma unroll
                for (int r = 0; r < 4; ++r)
                    acc[mt][nt][r] += accm[mt][nt][r];
        __syncthreads();
    }
#undef ISSUE_STAGE

    const int r0 = lane >> 2;
    const int c0 = (lane & 3) * 2;
#pragma unroll
    for (int mt = 0; mt < 2; ++mt) {
#pragma unroll
        for (int nt = 0; nt < 4; ++nt) {
            int col = n0 + warp_n*32 + nt*8 + c0;
            float b0 = bias[col], b1 = bias[col + 1];
            int row_t = m0 + warp_m*32 + mt*16 + r0;
            float v00 = (acc[mt][nt][0]*s1 + b0)*s2, v01 = (acc[mt][nt][1]*s1 + b1)*s2;
            float v10 = (acc[mt][nt][2]*s1 + b0)*s2, v11 = (acc[mt][nt][3]*s1 + b1)*s2;
            if (outH) {
                unsigned short h0,l0,h1,l1;
                split2(v00,h0,l0); split2(v01,h1,l1);
                *(unsigned*)(outH + (size_t)row_t*768 + col) = (unsigned)h0 | ((unsigned)h1<<16);
                *(unsigned*)(outL + (size_t)row_t*768 + col) = (unsigned)l0 | ((unsigned)l1<<16);
                split2(v10,h0,l0); split2(v11,h1,l1);
                *(unsigned*)(outH + (size_t)(row_t+8)*768 + col) = (unsigned)h0 | ((unsigned)h1<<16);
                *(unsigned*)(outL + (size_t)(row_t+8)*768 + col) = (unsigned)l0 | ((unsigned)l1<<16);
            } else {
                *(float2*)(C + (size_t)row_t*768 + col)       = make_float2(v00, v01);
                *(float2*)(C + (size_t)(row_t + 8)*768 + col) = make_float2(v10, v11);
            }
        }
    }
}

// merged projection GEMM: blockIdx.z selects (Q,K,V)
__global__ __launch_bounds__(512) void proj_gemm_kernel(
    const float* __restrict__ bq, const float* __restrict__ bk,
    const float* __restrict__ bv)
{
    const int z = blockIdx.z;
    const unsigned short* sA = g_sA3 + (size_t)z*2*ASZ;
    const unsigned short* sW = g_sW3 + (size_t)z*2*WSZ;
    const float* bias = (z == 0) ? bq : (z == 1) ? bk : bv;
    float s2 = (z == 0) ? 0.125f : 1.0f;
    unsigned short* oh = (z == 0) ? g_pQh : (z == 1) ? g_pKh : g_pVh;
    unsigned short* ol = (z == 0) ? g_pQl : (z == 1) ? g_pKl : g_pVl;
    gemm_core(sA, sW, bias, 1.0f, s2, nullptr, oh, ol);
}

// output projection GEMM
__global__ __launch_bounds__(512) void wo_gemm_kernel(
    const float* __restrict__ bo, float* __restrict__ out)
{
    gemm_core(g_sA3, g_sW3, bo, 1.0f/64.0f, 1.0f, out, nullptr, nullptr);
}

// ---------------------------------------------------------------------------
// fp16x3 MMA dilated flash attention (validated R14 — unchanged).
// ---------------------------------------------------------------------------
#define QH_B 0u
#define QL_B 18432u
#define KH_B 36864u
#define KL_B 46080u
#define VH_B 55296u
#define VL_B 64512u
#define PH_B 73728u
#define PL_B 92160u
#define ATTN_SMEM_BYTES 110592

__global__ __launch_bounds__(256) void attn_kernel()
{
    extern __shared__ unsigned short smh[];
    const int tid  = threadIdx.x;
    const int lane = tid & 31;
    const int warp = tid >> 5;

    const int inst = blockIdx.y;
    int grp, b, seg, hl;
    if (inst < 32)      { grp = 0; b = inst >> 4;        seg = (inst >> 2) & 3; hl = inst & 3; }
    else if (inst < 48) { int r = inst - 32; grp = 1; b = r >> 3; seg = (r >> 2) & 1; hl = r & 3; }
    else                { int r = inst - 48; grp = 2; b = r >> 2; seg = 0;            hl = r & 3; }
    const int rate = 1 << grp;
    const int slen = 2048 << grp;
    const int off  = grp;
    const int head = grp*4 + hl;
    const int q0   = blockIdx.x * 128;

    const size_t baseH = (size_t)b*NN*EE + (size_t)(seg*slen + off)*EE + head*DD;
    const int strideE = rate * EE;

    const unsigned smb = (unsigned)__cvta_generic_to_shared(smh);
    char* smc = (char*)smh;

#pragma unroll
    for (int i = 0; i < 4; ++i) {
        int idx = tid + i*256;
        int row = idx >> 3, c = idx & 7;
        size_t src = baseH + (size_t)(q0 + row)*strideE + c*8;
        *(uint4*)(smc + QH_B + row*144 + c*16) = *(const uint4*)(g_pQh + src);
        *(uint4*)(smc + QL_B + row*144 + c*16) = *(const uint4*)(g_pQl + src);
    }

    const unsigned aQH = smb + QH_B + (unsigned)((warp*16 + (lane & 15))*144) + ((lane >> 4) << 4);
    const unsigned aQL = aQH + (QL_B - QH_B);
    const unsigned bKH = smb + KH_B + (unsigned)((lane & 15)*144) + ((lane >> 4) << 4);
    const unsigned bKL = bKH + (KL_B - KH_B);
    const unsigned aPH = smb + PH_B + (unsigned)((warp*16 + (lane & 15))*144) + ((lane >> 4) << 4);
    const unsigned aPL = aPH + (PL_B - PH_B);

    float O[8][4];
#pragma unroll
    for (int nt = 0; nt < 8; ++nt)
#pragma unroll
        for (int r = 0; r < 4; ++r) O[nt][r] = 0.f;
    float mi0 = -1e30f, mi1 = -1e30f, li0 = 0.f, li1 = 0.f;

    const int r0 = lane >> 2;
    const int c0 = (lane & 3)*2;

    for (int kt = 0; kt < 32; ++kt) {
        const int k0 = kt*64;
        __syncthreads();
#pragma unroll
        for (int i = 0; i < 8; ++i) {
            int idx = tid + i*256;
            int arr = idx >> 9;
            int rem = idx & 511;
            int row = rem >> 3, c = rem & 7;
            size_t src = baseH + (size_t)(k0 + row)*strideE + c*8;
            const unsigned short* sp = (arr == 0) ? g_pKh : (arr == 1) ? g_pKl
                                     : (arr == 2) ? g_pVh : g_pVl;
            unsigned dst = (arr == 0) ? KH_B : (arr == 1) ? KL_B
                         : (arr == 2) ? VH_B : VL_B;
            *(uint4*)(smc + dst + row*144 + c*16) = *(const uint4*)(sp + src);
        }
        __syncthreads();

        float accm[8][4];
#pragma unroll
        for (int ks = 0; ks < 4; ++ks) {
            unsigned ah[4], al[4];
            ldsm4(ah, aQH + ks*32);
            ldsm4(al, aQL + ks*32);
#pragma unroll
            for (int p = 0; p < 4; ++p) {
                unsigned bh[4], bl[4];
                ldsm4(bh, bKH + p*(16*144) + ks*32);
                ldsm4(bl, bKL + p*(16*144) + ks*32);
#pragma unroll
                for (int h = 0; h < 2; ++h) {
                    float* ac = accm[p*2 + h];
                    if (ks == 0) mma_fp16_z(ac, ah, bl[h], bl[h+2]);
                    else         mma_fp16(ac, ah, bl[h], bl[h+2]);
                    mma_fp16(ac, al, bh[h], bh[h+2]);
                    mma_fp16(ac, ah, bh[h], bh[h+2]);
                }
            }
        }

        float mx0 = -1e30f, mx1 = -1e30f;
#pragma unroll
        for (int nt = 0; nt < 8; ++nt) {
            mx0 = fmaxf(mx0, fmaxf(accm[nt][0], accm[nt][1]));
            mx1 = fmaxf(mx1, fmaxf(accm[nt][2], accm[nt][3]));
        }
        mx0 = fmaxf(mx0, __shfl_xor_sync(0xffffffffu, mx0, 1));
        mx0 = fmaxf(mx0, __shfl_xor_sync(0xffffffffu, mx0, 2));
        mx1 = fmaxf(mx1, __shfl_xor_sync(0xffffffffu, mx1, 1));
        mx1 = fmaxf(mx1, __shfl_xor_sync(0xffffffffu, mx1, 2));
        float mn0 = fmaxf(mi0, mx0), mn1 = fmaxf(mi1, mx1);
        float cr0 = __expf(mi0 - mn0), cr1 = __expf(mi1 - mn1);
        mi0 = mn0; mi1 = mn1;
        float rs0 = 0.f, rs1 = 0.f;
#pragma unroll
        for (int nt = 0; nt < 8; ++nt) {
            float p00 = __expf(accm[nt][0] - mn0);
            float p01 = __expf(accm[nt][1] - mn0);
            float p10 = __expf(accm[nt][2] - mn1);
            float p11 = __expf(accm[nt][3] - mn1);
            rs0 += p00 + p01; rs1 += p10 + p11;
            unsigned short h0,l0,h1,l1;
            int colh = nt*8 + c0;
            split2(p00,h0,l0); split2(p01,h1,l1);
            *(unsigned*)(smc + PH_B + (warp*16 + r0)*144 + colh*2) = (unsigned)h0 | ((unsigned)h1<<16);
            *(unsigned*)(smc + PL_B + (warp*16 + r0)*144 + colh*2) = (unsigned)l0 | ((unsigned)l1<<16);
            split2(p10,h0,l0); split2(p11,h1,l1);
            *(unsigned*)(smc + PH_B + (warp*16 + r0 + 8)*144 + colh*2) = (unsigned)h0 | ((unsigned)h1<<16);
            *(unsigned*)(smc + PL_B + (warp*16 + r0 + 8)*144 + colh*2) = (unsigned)l0 | ((unsigned)l1<<16);
        }
        rs0 += __shfl_xor_sync(0xffffffffu, rs0, 1);
        rs0 += __shfl_xor_sync(0xffffffffu, rs0, 2);
        rs1 += __shfl_xor_sync(0xffffffffu, rs1, 1);
        rs1 += __shfl_xor_sync(0xffffffffu, rs1, 2);
        li0 = li0*cr0 + rs0;
        li1 = li1*cr1 + rs1;
        __syncwarp();

#pragma unroll
        for (int ks = 0; ks < 4; ++ks) {
            unsigned ah[4], al[4];
            ldsm4(ah, aPH + ks*32);
            ldsm4(al, aPL + ks*32);
#pragma unroll
            for (int p = 0; p < 4; ++p) {
                unsigned bh[4], bl[4];
                unsigned vaddr = smb + VH_B + (unsigned)(((lane & 15) + ks*16)*144)
                               + ((lane >> 4) << 4) + p*32;
                ldsm4t(bh, vaddr);
                ldsm4t(bl, vaddr + (VL_B - VH_B));
#pragma unroll
                for (int h = 0; h < 2; ++h) {
                    float* ac = accm[p*2 + h];
                    if (ks == 0) mma_fp16_z(ac, ah, bl[2*h], bl[2*h+1]);
                    else         mma_fp16(ac, ah, bl[2*h], bl[2*h+1]);
                    mma_fp16(ac, al, bh[2*h], bh[2*h+1]);
                    mma_fp16(ac, ah, bh[2*h], bh[2*h+1]);
                }
            }
        }
#pragma unroll
        for (int nt = 0; nt < 8; ++nt) {
            O[nt][0] = O[nt][0]*cr0 + accm[nt][0];
            O[nt][1] = O[nt][1]*cr0 + accm[nt][1];
            O[nt][2] = O[nt][2]*cr1 + accm[nt][2];
            O[nt][3] = O[nt][3]*cr1 + accm[nt][3];
        }
    }

    float inv0 = 1.f/li0, inv1 = 1.f/li1;
    const int ma = q0 + warp*16 + r0;
#pragma unroll
    for (int nt = 0; nt < 8; ++nt) {
        int col = nt*8 + c0;
        *(float2*)(g_O4 + baseH + (size_t)ma*strideE + col) =
            make_float2(O[nt][0]*inv0, O[nt][1]*inv0);
        *(float2*)(g_O4 + baseH + (size_t)(ma + 8)*strideE + col) =
            make_float2(O[nt][2]*inv1, O[nt][3]*inv1);
    }
}

// ---------------------------------------------------------------------------
// denom[b,c] = sum_n O4[b,n,c]; g_inv = 64/denom (fp16-range guard; 1/64 via s1)
// ---------------------------------------------------------------------------
__global__ void colsum_part_kernel()
{
    int chunk = blockIdx.x;
    int bc    = blockIdx.y;
    int b  = bc / 3;
    int c  = (bc % 3)*256 + threadIdx.x;
    const float* p = g_O4 + ((size_t)b*NN + chunk*256)*EE + c;
    float s = 0.f;
#pragma unroll 8
    for (int n = 0; n < 256; ++n) {
        s += *p;
        p += EE;
    }
    g_part[chunk*(BB*EE) + b*EE + c] = s;
}

__global__ void colsum_reduce_kernel()
{
    int i = blockIdx.x*256 + threadIdx.x;
    float s = 0.f;
#pragma unroll
    for (int ch = 0; ch < 32; ++ch) s += g_part[ch*(BB*EE) + i];
    g_inv[i] = 64.0f / s;
}

// ---------------------------------------------------------------------------
extern "C" void kernel_launch(void* const* d_in, const int* in_sizes, int n_in,
                              void* d_out, int out_size)
{
    const float* query = (const float*)d_in[0];
    const float* key   = (const float*)d_in[1];
    const float* value = (const float*)d_in[2];
    const float* Wq = (const float*)d_in[3];
    const float* bq = (const float*)d_in[4];
    const float* Wk = (const float*)d_in[5];
    const float* bk = (const float*)d_in[6];
    const float* Wv = (const float*)d_in[7];
    const float* bv = (const float*)d_in[8];
    const float* Wo = (const float*)d_in[9];
    const float* bo = (const float*)d_in[10];
    float* out = (float*)d_out;

    cudaFuncSetAttribute(attn_kernel,
                         cudaFuncAttributeMaxDynamicSharedMemorySize,
                         ATTN_SMEM_BYTES);
    cudaFuncSetAttribute(proj_gemm_kernel,
                         cudaFuncAttributeMaxDynamicSharedMemorySize,
                         GEMM_SMEM_BYTES);
    cudaFuncSetAttribute(wo_gemm_kernel,
                         cudaFuncAttributeMaxDynamicSharedMemorySize,
                         GEMM_SMEM_BYTES);

    // 1. zero scatter buffer
    zero_O4_kernel<<<12288, 256>>>();

    // 2. merged splits + merged projection GEMM (Q scaled 1/8 in epilogue)
    splitW3_kernel<<<dim3(576, 3), 256>>>(Wq, Wk, Wv);
    splitA3_kernel<<<dim3(12288, 3), 256>>>(query, key, value);
    proj_gemm_kernel<<<dim3(6, 128, 3), 512, GEMM_SMEM_BYTES>>>(bq, bk, bv);

    // 3. dilated attention on tensor cores (56 instances x 16 q-tiles)
    attn_kernel<<<dim3(16, 56), 256, ATTN_SMEM_BYTES>>>();

    // 4. sequence-sum normalization factors (64/denom)
    colsum_part_kernel<<<dim3(32, 6), 256>>>();
    colsum_reduce_kernel<<<6, 256>>>();

    // 5. output projection; 64/denom folded into A-split, 1/64 via s1
    splitW1_kernel<<<576, 256>>>(Wo);
    splitA_cs_kernel<<<12288, 256>>>();
    wo_gemm_kernel<<<dim3(6, 128), 512, GEMM_SMEM_BYTES>>>(bo, out);
}

// round 17
// speedup vs baseline: 2.3342x; 1.0149x over previous
#include <cuda_runtime.h>
#include <cuda_fp16.h>
#include <math.h>
#include <stdint.h>

// Problem constants
#define BB 2
#define NN 8192
#define EE 768
#define HH 12
#define DD 64
#define MTOT (BB*NN)        // 16384

// Scratch (device globals: allocation-guard safe)
__device__ float g_O4[BB*NN*EE];
__device__ float g_part[32*BB*EE];
__device__ float g_inv[BB*EE];

#define ASZ (MTOT*EE)
#define WSZ (EE*EE)
// 3-slot split planes: slot z holds [plane0, plane1] contiguously
__device__ unsigned short g_sA3[3*2*ASZ];
__device__ unsigned short g_sW3[3*2*WSZ];
// Q/K/V fp16 hi/lo planes (written by projection GEMM epilogues)
__device__ unsigned short g_pQh[ASZ], g_pQl[ASZ];
__device__ unsigned short g_pKh[ASZ], g_pKl[ASZ];
__device__ unsigned short g_pVh[ASZ], g_pVl[ASZ];

// ---------------------------------------------------------------------------
__global__ void zero_O4_kernel() {
    size_t i = (size_t)blockIdx.x * blockDim.x + threadIdx.x;
    ((float4*)g_O4)[i] = make_float4(0.f, 0.f, 0.f, 0.f);
}

// ---------------------------------------------------------------------------
// fp16 2-way split: x ~ a + b
// ---------------------------------------------------------------------------
__device__ __forceinline__ void split2(float x, unsigned short &a, unsigned short &b) {
    __half ha = __float2half_rn(x);
    float r1 = x - __half2float(ha);
    __half hb = __float2half_rn(r1);
    a = __half_as_ushort(ha);
    b = __half_as_ushort(hb);
}

__global__ void splitA3_kernel(const float* __restrict__ q,
                               const float* __restrict__ k,
                               const float* __restrict__ v) {
    int i = blockIdx.x*256 + threadIdx.x;
    const float* A = (blockIdx.y == 0) ? q : (blockIdx.y == 1) ? k : v;
    unsigned short* dst = g_sA3 + (size_t)blockIdx.y*2*ASZ;
    float4 av = ((const float4*)A)[i];
    ushort4 sa, sb;
    split2(av.x, sa.x, sb.x); split2(av.y, sa.y, sb.y);
    split2(av.z, sa.z, sb.z); split2(av.w, sa.w, sb.w);
    ((ushort4*)dst)[i]         = sa;
    ((ushort4*)(dst + ASZ))[i] = sb;
}

__global__ void splitA_cs_kernel() {
    int i = blockIdx.x*256 + threadIdx.x;
    float4 av = ((const float4*)g_O4)[i];
    int kq = i % 192;
    int m  = i / 192;
    float4 cs = ((const float4*)g_inv)[(m >> 13)*192 + kq];
    av.x *= cs.x; av.y *= cs.y; av.z *= cs.z; av.w *= cs.w;
    ushort4 sa, sb;
    split2(av.x, sa.x, sb.x); split2(av.y, sa.y, sb.y);
    split2(av.z, sa.z, sb.z); split2(av.w, sa.w, sb.w);
    ((ushort4*)g_sA3)[i]         = sa;
    ((ushort4*)(g_sA3 + ASZ))[i] = sb;
}

__global__ void splitW3_kernel(const float* __restrict__ wq,
                               const float* __restrict__ wk,
                               const float* __restrict__ wv) {
    int i = blockIdx.x*256 + threadIdx.x;
    const float* W = (blockIdx.y == 0) ? wq : (blockIdx.y == 1) ? wk : wv;
    unsigned short* dst = g_sW3 + (size_t)blockIdx.y*2*WSZ;
    float4 wvv = ((const float4*)W)[i];
    ushort4 sa, sb;
    split2(wvv.x, sa.x, sb.x); split2(wvv.y, sa.y, sb.y);
    split2(wvv.z, sa.z, sb.z); split2(wvv.w, sa.w, sb.w);
    ((ushort4*)dst)[i]         = sa;
    ((ushort4*)(dst + WSZ))[i] = sb;
}

__global__ void splitW1_kernel(const float* __restrict__ W) {
    int i = blockIdx.x*256 + threadIdx.x;
    float4 wvv = ((const float4*)W)[i];
    ushort4 sa, sb;
    split2(wvv.x, sa.x, sb.x); split2(wvv.y, sa.y, sb.y);
    split2(wvv.z, sa.z, sb.z); split2(wvv.w, sa.w, sb.w);
    ((ushort4*)g_sW3)[i]         = sa;
    ((ushort4*)(g_sW3 + WSZ))[i] = sb;
}

// ---------------------------------------------------------------------------
// MMA helpers
// ---------------------------------------------------------------------------
__device__ __forceinline__ void mma_fp16(float* acc, const unsigned* a, unsigned b0, unsigned b1) {
    asm volatile(
        "mma.sync.aligned.m16n8k16.row.col.f32.f16.f16.f32 "
        "{%0,%1,%2,%3}, {%4,%5,%6,%7}, {%8,%9}, {%0,%1,%2,%3};"
        : "+f"(acc[0]), "+f"(acc[1]), "+f"(acc[2]), "+f"(acc[3])
        : "r"(a[0]), "r"(a[1]), "r"(a[2]), "r"(a[3]), "r"(b0), "r"(b1));
}
__device__ __forceinline__ void mma_fp16_z(float* d, const unsigned* a, unsigned b0, unsigned b1) {
    asm volatile(
        "mma.sync.aligned.m16n8k16.row.col.f32.f16.f16.f32 "
        "{%0,%1,%2,%3}, {%4,%5,%6,%7}, {%8,%9}, {%10,%11,%12,%13};"
        : "=f"(d[0]), "=f"(d[1]), "=f"(d[2]), "=f"(d[3])
        : "r"(a[0]), "r"(a[1]), "r"(a[2]), "r"(a[3]), "r"(b0), "r"(b1),
          "f"(0.f), "f"(0.f), "f"(0.f), "f"(0.f));
}
__device__ __forceinline__ void ldsm4(unsigned* d, unsigned addr) {
    asm volatile("ldmatrix.sync.aligned.m8n8.x4.shared.b16 {%0,%1,%2,%3}, [%4];"
                 : "=r"(d[0]), "=r"(d[1]), "=r"(d[2]), "=r"(d[3]) : "r"(addr));
}
__device__ __forceinline__ void ldsm4t(unsigned* d, unsigned addr) {
    asm volatile("ldmatrix.sync.aligned.m8n8.x4.trans.shared.b16 {%0,%1,%2,%3}, [%4];"
                 : "=r"(d[0]), "=r"(d[1]), "=r"(d[2]), "=r"(d[3]) : "r"(addr));
}
__device__ __forceinline__ void cp_async16(unsigned saddr, const void* g) {
    asm volatile("cp.async.ca.shared.global [%0], [%1], 16;"
                 :: "r"(saddr), "l"(g) : "memory");
}

// ---------------------------------------------------------------------------
// fp16x3 GEMM core: 4-stage cp.async pipeline + fragment software pipeline.
// One barrier per K-block (bottom barrier proven redundant).
// ---------------------------------------------------------------------------
#define BLDA 40
#define SPL  (128*BLDA)
#define SPLB (SPL*2u)
#define STGB (4*SPLB)              // 40960 bytes per stage
#define NSTAGE 4
#define GEMM_SMEM_BYTES (NSTAGE*STGB)   // 163840

__device__ __forceinline__ void gemm_core(
    const unsigned short* __restrict__ sA,
    const unsigned short* __restrict__ sW,
    const float* __restrict__ bias, float s1, float s2,
    float* __restrict__ C, unsigned short* __restrict__ outH,
    unsigned short* __restrict__ outL)
{
    extern __shared__ unsigned short smu[];
    const int tid  = threadIdx.x;
    const int lane = tid & 31;
    const int wid  = tid >> 5;
    const int warp_m = wid & 3;
    const int warp_n = wid >> 2;
    const int m0 = blockIdx.y * 128;
    const int n0 = blockIdx.x * 128;
    const int lrow = tid >> 2;
    const int lcol = tid & 3;

    float acc[2][4][4];
    float accm[2][4][4];
#pragma unroll
    for (int mt = 0; mt < 2; ++mt)
#pragma unroll
        for (int nt = 0; nt < 4; ++nt)
#pragma unroll
            for (int r = 0; r < 4; ++r) acc[mt][nt][r] = 0.f;

    const unsigned smbase = (unsigned)__cvta_generic_to_shared(smu);
    const unsigned a_off = (unsigned)((warp_m*32 + (lane & 15))*80) + ((lane >> 4) << 4);
    const unsigned b_off = (unsigned)((warp_n*32 + (lane & 15))*80) + ((lane >> 4) << 4);
    const unsigned dst_off = (unsigned)(lrow*80 + lcol*16);

    const unsigned short* pA = sA + (size_t)(m0 + lrow)*768 + lcol*8;
    const unsigned short* pW = sW + (size_t)(n0 + lrow)*768 + lcol*8;

#define ISSUE_STAGE(t)                                                          \
    {                                                                           \
        if ((t) < 24) {                                                         \
            const unsigned dst_ = smbase + (unsigned)((t) % NSTAGE)*STGB + dst_off; \
            const unsigned short* a_ = pA + (t)*32;                             \
            const unsigned short* w_ = pW + (t)*32;                             \
            cp_async16(dst_,          a_);                                      \
            cp_async16(dst_ + SPLB,   a_ + ASZ);                                \
            cp_async16(dst_ + 2*SPLB, w_);                                      \
            cp_async16(dst_ + 3*SPLB, w_ + WSZ);                                \
        }                                                                       \
        asm volatile("cp.async.commit_group;" ::: "memory");                    \
    }

    ISSUE_STAGE(0); ISSUE_STAGE(1); ISSUE_STAGE(2);

    const int SA[3] = {0, 1, 0};
    const int SB[3] = {1, 0, 0};

    for (int t = 0; t < 24; ++t) {
        asm volatile("cp.async.wait_group 2;" ::: "memory");
        __syncthreads();
        ISSUE_STAGE(t + 3);

        const unsigned stg = smbase + (unsigned)(t % NSTAGE)*STGB;

        unsigned af[2][2][2][4];
        unsigned bf[2][2][4];
#pragma unroll
        for (int mt = 0; mt < 2; ++mt)
#pragma unroll
            for (int s = 0; s < 2; ++s)
                ldsm4(af[0][mt][s], stg + s*SPLB + a_off + mt*(16*80));
#pragma unroll
        for (int s = 0; s < 2; ++s)
            ldsm4(bf[0][s], stg + (2+s)*SPLB + b_off);

#pragma unroll
        for (int u = 0; u < 4; ++u) {
            const int ks = u >> 1, p = u & 1, buf = u & 1;
            if (u < 3) {
                const int nks = (u+1) >> 1, np = (u+1) & 1;
#pragma unroll
                for (int s = 0; s < 2; ++s)
                    ldsm4(bf[buf^1][s], stg + (2+s)*SPLB + b_off + np*(16*80) + nks*32);
                if (u == 1) {
#pragma unroll
                    for (int mt = 0; mt < 2; ++mt)
#pragma unroll
                        for (int s = 0; s < 2; ++s)
                            ldsm4(af[1][mt][s], stg + s*SPLB + a_off + mt*(16*80) + 32);
                }
            }
#pragma unroll
            for (int prod = 0; prod < 3; ++prod) {
                const int sa = SA[prod], sb = SB[prod];
#pragma unroll
                for (int mt = 0; mt < 2; ++mt)
#pragma unroll
                    for (int h = 0; h < 2; ++h) {
                        float* ac = accm[mt][p*2 + h];
                        if (ks == 0 && prod == 0)
                            mma_fp16_z(ac, af[ks][mt][sa], bf[buf][sb][h], bf[buf][sb][h+2]);
                        else
                            mma_fp16(ac, af[ks][mt][sa], bf[buf][sb][h], bf[buf][sb][h+2]);
                    }
            }
        }
#pragma unroll
        for (int mt = 0; mt < 2; ++mt)
#pragma unroll
            for (int nt = 0; nt < 4; ++nt)
#pragma unroll
                for (int r = 0; r < 4; ++r)
                    acc[mt][nt][r] += accm[mt][nt][r];
        // bottom barrier removed: next iter's top barrier provides the ordering
    }
#undef ISSUE_STAGE

    const int r0 = lane >> 2;
    const int c0 = (lane & 3) * 2;
#pragma unroll
    for (int mt = 0; mt < 2; ++mt) {
#pragma unroll
        for (int nt = 0; nt < 4; ++nt) {
            int col = n0 + warp_n*32 + nt*8 + c0;
            float b0 = bias[col], b1 = bias[col + 1];
            int row_t = m0 + warp_m*32 + mt*16 + r0;
            float v00 = (acc[mt][nt][0]*s1 + b0)*s2, v01 = (acc[mt][nt][1]*s1 + b1)*s2;
            float v10 = (acc[mt][nt][2]*s1 + b0)*s2, v11 = (acc[mt][nt][3]*s1 + b1)*s2;
            if (outH) {
                unsigned short h0,l0,h1,l1;
                split2(v00,h0,l0); split2(v01,h1,l1);
                *(unsigned*)(outH + (size_t)row_t*768 + col) = (unsigned)h0 | ((unsigned)h1<<16);
                *(unsigned*)(outL + (size_t)row_t*768 + col) = (unsigned)l0 | ((unsigned)l1<<16);
                split2(v10,h0,l0); split2(v11,h1,l1);
                *(unsigned*)(outH + (size_t)(row_t+8)*768 + col) = (unsigned)h0 | ((unsigned)h1<<16);
                *(unsigned*)(outL + (size_t)(row_t+8)*768 + col) = (unsigned)l0 | ((unsigned)l1<<16);
            } else {
                *(float2*)(C + (size_t)row_t*768 + col)       = make_float2(v00, v01);
                *(float2*)(C + (size_t)(row_t + 8)*768 + col) = make_float2(v10, v11);
            }
        }
    }
}

__global__ __launch_bounds__(512) void proj_gemm_kernel(
    const float* __restrict__ bq, const float* __restrict__ bk,
    const float* __restrict__ bv)
{
    const int z = blockIdx.z;
    const unsigned short* sA = g_sA3 + (size_t)z*2*ASZ;
    const unsigned short* sW = g_sW3 + (size_t)z*2*WSZ;
    const float* bias = (z == 0) ? bq : (z == 1) ? bk : bv;
    float s2 = (z == 0) ? 0.125f : 1.0f;
    unsigned short* oh = (z == 0) ? g_pQh : (z == 1) ? g_pKh : g_pVh;
    unsigned short* ol = (z == 0) ? g_pQl : (z == 1) ? g_pKl : g_pVl;
    gemm_core(sA, sW, bias, 1.0f, s2, nullptr, oh, ol);
}

__global__ __launch_bounds__(512) void wo_gemm_kernel(
    const float* __restrict__ bo, float* __restrict__ out)
{
    gemm_core(g_sA3, g_sW3, bo, 1.0f/64.0f, 1.0f, out, nullptr, nullptr);
}

// ---------------------------------------------------------------------------
// fp16x3 MMA dilated flash attention — 512 threads, 256 q-rows per CTA.
// Warp w owns q-rows [w*16, w*16+16); all 16 warps share each K/V chunk.
// Same per-warp arithmetic as the validated R14 kernel (bit-identical).
// ---------------------------------------------------------------------------
#define QH_B 0u
#define QL_B 36864u
#define KH_B 73728u
#define KL_B 82944u
#define VH_B 92160u
#define VL_B 101376u
#define PH_B 110592u
#define PL_B 147456u
#define ATTN_SMEM_BYTES 184320

__global__ __launch_bounds__(512) void attn_kernel()
{
    extern __shared__ unsigned short smh[];
    const int tid  = threadIdx.x;
    const int lane = tid & 31;
    const int warp = tid >> 5;          // 0..15

    const int inst = blockIdx.y;
    int grp, b, seg, hl;
    if (inst < 32)      { grp = 0; b = inst >> 4;        seg = (inst >> 2) & 3; hl = inst & 3; }
    else if (inst < 48) { int r = inst - 32; grp = 1; b = r >> 3; seg = (r >> 2) & 1; hl = r & 3; }
    else                { int r = inst - 48; grp = 2; b = r >> 2; seg = 0;            hl = r & 3; }
    const int rate = 1 << grp;
    const int slen = 2048 << grp;
    const int off  = grp;
    const int head = grp*4 + hl;
    const int q0   = blockIdx.x * 256;

    const size_t baseH = (size_t)b*NN*EE + (size_t)(seg*slen + off)*EE + head*DD;
    const int strideE = rate * EE;

    const unsigned smb = (unsigned)__cvta_generic_to_shared(smh);
    char* smc = (char*)smh;

    // Load Q tile: 256 rows x 8 chunks, hi+lo planes
#pragma unroll
    for (int i = 0; i < 4; ++i) {
        int idx = tid + i*512;           // 2048 = 256 rows x 8 chunks
        int row = idx >> 3, c = idx & 7;
        size_t src = baseH + (size_t)(q0 + row)*strideE + c*8;
        *(uint4*)(smc + QH_B + row*144 + c*16) = *(const uint4*)(g_pQh + src);
        *(uint4*)(smc + QL_B + row*144 + c*16) = *(const uint4*)(g_pQl + src);
    }

    const unsigned aQH = smb + QH_B + (unsigned)((warp*16 + (lane & 15))*144) + ((lane >> 4) << 4);
    const unsigned aQL = aQH + (QL_B - QH_B);
    const unsigned bKH = smb + KH_B + (unsigned)((lane & 15)*144) + ((lane >> 4) << 4);
    const unsigned bKL = bKH + (KL_B - KH_B);
    const unsigned aPH = smb + PH_B + (unsigned)((warp*16 + (lane & 15))*144) + ((lane >> 4) << 4);
    const unsigned aPL = aPH + (PL_B - PH_B);

    float O[8][4];
#pragma unroll
    for (int nt = 0; nt < 8; ++nt)
#pragma unroll
        for (int r = 0; r < 4; ++r) O[nt][r] = 0.f;
    float mi0 = -1e30f, mi1 = -1e30f, li0 = 0.f, li1 = 0.f;

    const int r0 = lane >> 2;
    const int c0 = (lane & 3)*2;

    for (int kt = 0; kt < 32; ++kt) {
        const int k0 = kt*64;
        __syncthreads();
        // load K,V chunk (hi/lo): 4 arrays x 64 rows x 8 chunks = 2048 uint4
#pragma unroll
        for (int i = 0; i < 4; ++i) {
            int idx = tid + i*512;
            int arr = idx >> 9;
            int rem = idx & 511;
            int row = rem >> 3, c = rem & 7;
            size_t src = baseH + (size_t)(k0 + row)*strideE + c*8;
            const unsigned short* sp = (arr == 0) ? g_pKh : (arr == 1) ? g_pKl
                                     : (arr == 2) ? g_pVh : g_pVl;
            unsigned dst = (arr == 0) ? KH_B : (arr == 1) ? KL_B
                         : (arr == 2) ? VH_B : VL_B;
            *(uint4*)(smc + dst + row*144 + c*16) = *(const uint4*)(sp + src);
        }
        __syncthreads();

        float accm[8][4];
#pragma unroll
        for (int ks = 0; ks < 4; ++ks) {
            unsigned ah[4], al[4];
            ldsm4(ah, aQH + ks*32);
            ldsm4(al, aQL + ks*32);
#pragma unroll
            for (int p = 0; p < 4; ++p) {
                unsigned bh[4], bl[4];
                ldsm4(bh, bKH + p*(16*144) + ks*32);
                ldsm4(bl, bKL + p*(16*144) + ks*32);
#pragma unroll
                for (int h = 0; h < 2; ++h) {
                    float* ac = accm[p*2 + h];
                    if (ks == 0) mma_fp16_z(ac, ah, bl[h], bl[h+2]);
                    else         mma_fp16(ac, ah, bl[h], bl[h+2]);
                    mma_fp16(ac, al, bh[h], bh[h+2]);
                    mma_fp16(ac, ah, bh[h], bh[h+2]);
                }
            }
        }

        float mx0 = -1e30f, mx1 = -1e30f;
#pragma unroll
        for (int nt = 0; nt < 8; ++nt) {
            mx0 = fmaxf(mx0, fmaxf(accm[nt][0], accm[nt][1]));
            mx1 = fmaxf(mx1, fmaxf(accm[nt][2], accm[nt][3]));
        }
        mx0 = fmaxf(mx0, __shfl_xor_sync(0xffffffffu, mx0, 1));
        mx0 = fmaxf(mx0, __shfl_xor_sync(0xffffffffu, mx0, 2));
        mx1 = fmaxf(mx1, __shfl_xor_sync(0xffffffffu, mx1, 1));
        mx1 = fmaxf(mx1, __shfl_xor_sync(0xffffffffu, mx1, 2));
        float mn0 = fmaxf(mi0, mx0), mn1 = fmaxf(mi1, mx1);
        float cr0 = __expf(mi0 - mn0), cr1 = __expf(mi1 - mn1);
        mi0 = mn0; mi1 = mn1;
        float rs0 = 0.f, rs1 = 0.f;
#pragma unroll
        for (int nt = 0; nt < 8; ++nt) {
            float p00 = __expf(accm[nt][0] - mn0);
            float p01 = __expf(accm[nt][1] - mn0);
            float p10 = __expf(accm[nt][2] - mn1);
            float p11 = __expf(accm[nt][3] - mn1);
            rs0 += p00 + p01; rs1 += p10 + p11;
            unsigned short h0,l0,h1,l1;
            int colh = nt*8 + c0;
            split2(p00,h0,l0); split2(p01,h1,l1);
            *(unsigned*)(smc + PH_B + (warp*16 + r0)*144 + colh*2) = (unsigned)h0 | ((unsigned)h1<<16);
            *(unsigned*)(smc + PL_B + (warp*16 + r0)*144 + colh*2) = (unsigned)l0 | ((unsigned)l1<<16);
            split2(p10,h0,l0); split2(p11,h1,l1);
            *(unsigned*)(smc + PH_B + (warp*16 + r0 + 8)*144 + colh*2) = (unsigned)h0 | ((unsigned)h1<<16);
            *(unsigned*)(smc + PL_B + (warp*16 + r0 + 8)*144 + colh*2) = (unsigned)l0 | ((unsigned)l1<<16);
        }
        rs0 += __shfl_xor_sync(0xffffffffu, rs0, 1);
        rs0 += __shfl_xor_sync(0xffffffffu, rs0, 2);
        rs1 += __shfl_xor_sync(0xffffffffu, rs1, 1);
        rs1 += __shfl_xor_sync(0xffffffffu, rs1, 2);
        li0 = li0*cr0 + rs0;
        li1 = li1*cr1 + rs1;
        __syncwarp();

#pragma unroll
        for (int ks = 0; ks < 4; ++ks) {
            unsigned ah[4], al[4];
            ldsm4(ah, aPH + ks*32);
            ldsm4(al, aPL + ks*32);
#pragma unroll
            for (int p = 0; p < 4; ++p) {
                unsigned bh[4], bl[4];
                unsigned vaddr = smb + VH_B + (unsigned)(((lane & 15) + ks*16)*144)
                               + ((lane >> 4) << 4) + p*32;
                ldsm4t(bh, vaddr);
                ldsm4t(bl, vaddr + (VL_B - VH_B));
#pragma unroll
                for (int h = 0; h < 2; ++h) {
                    float* ac = accm[p*2 + h];
                    if (ks == 0) mma_fp16_z(ac, ah, bl[2*h], bl[2*h+1]);
                    else         mma_fp16(ac, ah, bl[2*h], bl[2*h+1]);
                    mma_fp16(ac, al, bh[2*h], bh[2*h+1]);
                    mma_fp16(ac, ah, bh[2*h], bh[2*h+1]);
                }
            }
        }
#pragma unroll
        for (int nt = 0; nt < 8; ++nt) {
            O[nt][0] = O[nt][0]*cr0 + accm[nt][0];
            O[nt][1] = O[nt][1]*cr0 + accm[nt][1];
            O[nt][2] = O[nt][2]*cr1 + accm[nt][2];
            O[nt][3] = O[nt][3]*cr1 + accm[nt][3];
        }
    }

    float inv0 = 1.f/li0, inv1 = 1.f/li1;
    const int ma = q0 + warp*16 + r0;
#pragma unroll
    for (int nt = 0; nt < 8; ++nt) {
        int col = nt*8 + c0;
        *(float2*)(g_O4 + baseH + (size_t)ma*strideE + col) =
            make_float2(O[nt][0]*inv0, O[nt][1]*inv0);
        *(float2*)(g_O4 + baseH + (size_t)(ma + 8)*strideE + col) =
            make_float2(O[nt][2]*inv1, O[nt][3]*inv1);
    }
}

// ---------------------------------------------------------------------------
// denom[b,c] = sum_n O4[b,n,c]; g_inv = 64/denom
// ---------------------------------------------------------------------------
__global__ void colsum_part_kernel()
{
    int chunk = blockIdx.x;
    int bc    = blockIdx.y;
    int b  = bc / 3;
    int c  = (bc % 3)*256 + threadIdx.x;
    const float* p = g_O4 + ((size_t)b*NN + chunk*256)*EE + c;
    float s = 0.f;
#pragma unroll 8
    for (int n = 0; n < 256; ++n) {
        s += *p;
        p += EE;
    }
    g_part[chunk*(BB*EE) + b*EE + c] = s;
}

__global__ void colsum_reduce_kernel()
{
    int i = blockIdx.x*256 + threadIdx.x;
    float s = 0.f;
#pragma unroll
    for (int ch = 0; ch < 32; ++ch) s += g_part[ch*(BB*EE) + i];
    g_inv[i] = 64.0f / s;
}

// ---------------------------------------------------------------------------
extern "C" void kernel_launch(void* const* d_in, const int* in_sizes, int n_in,
                              void* d_out, int out_size)
{
    const float* query = (const float*)d_in[0];
    const float* key   = (const float*)d_in[1];
    const float* value = (const float*)d_in[2];
    const float* Wq = (const float*)d_in[3];
    const float* bq = (const float*)d_in[4];
    const float* Wk = (const float*)d_in[5];
    const float* bk = (const float*)d_in[6];
    const float* Wv = (const float*)d_in[7];
    const float* bv = (const float*)d_in[8];
    const float* Wo = (const float*)d_in[9];
    const float* bo = (const float*)d_in[10];
    float* out = (float*)d_out;

    cudaFuncSetAttribute(attn_kernel,
                         cudaFuncAttributeMaxDynamicSharedMemorySize,
                         ATTN_SMEM_BYTES);
    cudaFuncSetAttribute(proj_gemm_kernel,
                         cudaFuncAttributeMaxDynamicSharedMemorySize,
                         GEMM_SMEM_BYTES);
    cudaFuncSetAttribute(wo_gemm_kernel,
                         cudaFuncAttributeMaxDynamicSharedMemorySize,
                         GEMM_SMEM_BYTES);

    // 1. zero scatter buffer
    zero_O4_kernel<<<12288, 256>>>();

    // 2. merged splits + merged projection GEMM (Q scaled 1/8 in epilogue)
    splitW3_kernel<<<dim3(576, 3), 256>>>(Wq, Wk, Wv);
    splitA3_kernel<<<dim3(12288, 3), 256>>>(query, key, value);
    proj_gemm_kernel<<<dim3(6, 128, 3), 512, GEMM_SMEM_BYTES>>>(bq, bk, bv);

    // 3. dilated attention on tensor cores (56 instances x 8 q-tiles of 256)
    attn_kernel<<<dim3(8, 56), 512, ATTN_SMEM_BYTES>>>();

    // 4. sequence-sum normalization factors (64/denom)
    colsum_part_kernel<<<dim3(32, 6), 256>>>();
    colsum_reduce_kernel<<<6, 256>>>();

    // 5. output projection; 64/denom folded into A-split, 1/64 via s1
    splitW1_kernel<<<576, 256>>>(Wo);
    splitA_cs_kernel<<<12288, 256>>>();
    wo_gemm_kernel<<<dim3(6, 128), 512, GEMM_SMEM_BYTES>>>(bo, out);
}